// round 1
// baseline (speedup 1.0000x reference)
#include <cuda_runtime.h>
#include <cstdint>
#include <cstddef>

// ---------------- problem-size caps (match reference) ----------------
#define NU_MAX 100000
#define NB_MAX 50000
#define C 64
#define H 128

// ---------------- device scratch (static, allocation-free) -----------
__device__ float g_u0[NU_MAX * C];
__device__ float g_b0[NB_MAX * C];
__device__ float g_u1[NU_MAX * C];
__device__ float g_b1[NB_MAX * C];
__device__ float g_u2[NU_MAX * C];
__device__ float g_b2[NB_MAX * C];
__device__ float g_uagg[NU_MAX * C];
__device__ float g_bagg[NB_MAX * C];
__device__ float g_ucnt[NU_MAX];
__device__ float g_bcnt[NB_MAX];
__device__ float g_up[NU_MAX * H];   // decoder user partials (incl. dec_b1)
__device__ float g_bp[NB_MAX * H];   // decoder book partials

// ---------------- utility kernels ----------------
__global__ void zero4_kernel(float4* __restrict__ p, long n4) {
    long i = (long)blockIdx.x * blockDim.x + threadIdx.x;
    long st = (long)gridDim.x * blockDim.x;
    float4 z = make_float4(0.f, 0.f, 0.f, 0.f);
    for (; i < n4; i += st) p[i] = z;
}

__global__ void count_kernel(const int* __restrict__ src, const int* __restrict__ dst,
                             float* __restrict__ ucnt, float* __restrict__ bcnt, int E) {
    int i = blockIdx.x * blockDim.x + threadIdx.x;
    if (i < E) {
        atomicAdd(ucnt + src[i], 1.0f);
        atomicAdd(bcnt + dst[i], 1.0f);
    }
}

// ---------------- input projections ----------------
__global__ void user_proj_kernel(const float* __restrict__ x, const float* __restrict__ w,
                                 const float* __restrict__ b, float* __restrict__ out, int n) {
    unsigned i = blockIdx.x * blockDim.x + threadIdx.x;
    if (i >= (unsigned)n * 64u) return;
    unsigned node = i >> 6, j = i & 63u;
    const float* xr = x + (size_t)node * 3;
    float x0 = __ldg(xr), x1 = __ldg(xr + 1), x2 = __ldg(xr + 2);
    out[i] = __ldg(b + j) + x0 * __ldg(w + j) + x1 * __ldg(w + 64 + j) + x2 * __ldg(w + 128 + j);
}

// book: [n,384] @ [384,64] + b, warp-per-node, weights chunked through SMEM
__global__ void book_proj_kernel(const float* __restrict__ x, const float* __restrict__ w,
                                 const float* __restrict__ bias, float* __restrict__ out, int n) {
    __shared__ __align__(16) float s_w[96 * 64];     // 24 KB weight chunk
    __shared__ __align__(16) float s_row[8][384];    // 12 KB x rows
    int lane = threadIdx.x & 31, wid = threadIdx.x >> 5;
    int node = blockIdx.x * 8 + wid;
    bool valid = node < n;
    if (valid) {
        const float4* xr = reinterpret_cast<const float4*>(x + (size_t)node * 384);
        float4* sr = reinterpret_cast<float4*>(s_row[wid]);
        for (int i = lane; i < 96; i += 32) sr[i] = __ldg(xr + i);
    }
    float2 acc = make_float2(0.f, 0.f);
    if (valid) { acc.x = __ldg(bias + lane * 2); acc.y = __ldg(bias + lane * 2 + 1); }
    for (int ch = 0; ch < 4; ch++) {
        __syncthreads();
        const float2* wsrc = reinterpret_cast<const float2*>(w + ch * 96 * 64);
        float2* wd = reinterpret_cast<float2*>(s_w);
        for (int i = threadIdx.x; i < 96 * 64 / 2; i += 256) wd[i] = __ldg(wsrc + i);
        __syncthreads();
        if (valid) {
            #pragma unroll 8
            for (int kk = 0; kk < 96; kk++) {
                float xv = s_row[wid][ch * 96 + kk];
                float2 wv = *reinterpret_cast<const float2*>(s_w + kk * 64 + lane * 2);
                acc.x += xv * wv.x;
                acc.y += xv * wv.y;
            }
        }
    }
    if (valid)
        *reinterpret_cast<float2*>(out + (size_t)node * 64 + lane * 2) = acc;
}

// ---------------- edge aggregation: scatter-add 64ch via vec4 red ----------------
__global__ void agg_kernel(const float* __restrict__ xsrc, const int* __restrict__ sidx,
                           const int* __restrict__ didx, float* __restrict__ agg, int E) {
    unsigned gid = blockIdx.x * blockDim.x + threadIdx.x;
    unsigned total = (unsigned)E * 16u;
    if (gid >= total) return;
    unsigned e = gid >> 4, c = gid & 15u;
    int s = __ldg(sidx + e);
    int d = __ldg(didx + e);
    float4 v = *reinterpret_cast<const float4*>(xsrc + (size_t)s * 64 + c * 4);
    float* dp = agg + (size_t)d * 64 + c * 4;
    asm volatile("red.global.add.v4.f32 [%0], {%1,%2,%3,%4};"
                 :: "l"(dp), "f"(v.x), "f"(v.y), "f"(v.z), "f"(v.w) : "memory");
}

// ---------------- SAGE node transform: out = (agg/cnt)@wl + b + x@wr [, relu] ----------------
template <bool RELU>
__global__ void sage_transform_kernel(const float* __restrict__ agg, const float* __restrict__ cnt,
                                      const float* __restrict__ xdst,
                                      const float* __restrict__ wl, const float* __restrict__ bias,
                                      const float* __restrict__ wr,
                                      float* __restrict__ out, int n) {
    __shared__ __align__(16) float s_wl[64 * 64];
    __shared__ __align__(16) float s_wr[64 * 64];
    __shared__ float s_b[64];
    __shared__ float s_rows[8][128];   // per-warp: mean[64] | x[64]
    for (int i = threadIdx.x; i < 64 * 64; i += blockDim.x) { s_wl[i] = wl[i]; s_wr[i] = wr[i]; }
    if (threadIdx.x < 64) s_b[threadIdx.x] = bias[threadIdx.x];
    __syncthreads();
    int lane = threadIdx.x & 31, wid = threadIdx.x >> 5;
    int node = blockIdx.x * 8 + wid;
    if (node >= n) return;
    float inv = 1.0f / fmaxf(__ldg(cnt + node), 1.0f);
    float2 m = *reinterpret_cast<const float2*>(agg + (size_t)node * 64 + lane * 2);
    float2 x = *reinterpret_cast<const float2*>(xdst + (size_t)node * 64 + lane * 2);
    s_rows[wid][lane * 2]      = m.x * inv;
    s_rows[wid][lane * 2 + 1]  = m.y * inv;
    s_rows[wid][64 + lane * 2]     = x.x;
    s_rows[wid][64 + lane * 2 + 1] = x.y;
    __syncwarp();
    float2 acc = make_float2(s_b[lane * 2], s_b[lane * 2 + 1]);
    #pragma unroll 8
    for (int k = 0; k < 64; k++) {
        float mk = s_rows[wid][k];
        float xk = s_rows[wid][64 + k];
        float2 wlv = *reinterpret_cast<const float2*>(s_wl + k * 64 + lane * 2);
        float2 wrv = *reinterpret_cast<const float2*>(s_wr + k * 64 + lane * 2);
        acc.x += mk * wlv.x + xk * wrv.x;
        acc.y += mk * wlv.y + xk * wrv.y;
    }
    if (RELU) { acc.x = fmaxf(acc.x, 0.f); acc.y = fmaxf(acc.y, 0.f); }
    *reinterpret_cast<float2*>(out + (size_t)node * 64 + lane * 2) = acc;
}

// ---------------- decoder precompute: out[n,128] = x[n,64] @ w[64,128] (+bias) ----------------
__global__ void dec_pre_kernel(const float* __restrict__ x, const float* __restrict__ w,
                               const float* __restrict__ bias, float* __restrict__ out, int n) {
    __shared__ __align__(16) float s_w[64 * 128];   // 32 KB
    __shared__ float s_rows[8][64];
    for (int i = threadIdx.x; i < 64 * 128; i += blockDim.x) s_w[i] = w[i];
    __syncthreads();
    int lane = threadIdx.x & 31, wid = threadIdx.x >> 5;
    int node = blockIdx.x * 8 + wid;
    if (node >= n) return;
    float2 xv = *reinterpret_cast<const float2*>(x + (size_t)node * 64 + lane * 2);
    s_rows[wid][lane * 2] = xv.x;
    s_rows[wid][lane * 2 + 1] = xv.y;
    __syncwarp();
    float4 acc;
    if (bias) acc = *reinterpret_cast<const float4*>(bias + lane * 4);
    else      acc = make_float4(0.f, 0.f, 0.f, 0.f);
    #pragma unroll 8
    for (int k = 0; k < 64; k++) {
        float xk = s_rows[wid][k];
        float4 wv = *reinterpret_cast<const float4*>(s_w + k * 128 + lane * 4);
        acc.x += xk * wv.x; acc.y += xk * wv.y; acc.z += xk * wv.z; acc.w += xk * wv.w;
    }
    *reinterpret_cast<float4*>(out + (size_t)node * 128 + lane * 4) = acc;
}

// ---------------- decoder edge kernel: out[e] = relu(Up[s]+Bp[d]) . w2 + b2 ----------------
__global__ void dec_edge_kernel(const float* __restrict__ Up, const float* __restrict__ Bp,
                                const int* __restrict__ ls, const int* __restrict__ ld,
                                const float* __restrict__ w2, const float* __restrict__ b2,
                                float* __restrict__ out, int m) {
    __shared__ float s_w2[128];
    if (threadIdx.x < 128) s_w2[threadIdx.x] = w2[threadIdx.x];
    __syncthreads();
    int warp = (blockIdx.x * blockDim.x + threadIdx.x) >> 5;
    int lane = threadIdx.x & 31;
    if (warp >= m) return;
    int s = __ldg(ls + warp);
    int d = __ldg(ld + warp);
    float4 a = *reinterpret_cast<const float4*>(Up + (size_t)s * 128 + lane * 4);
    float4 b = *reinterpret_cast<const float4*>(Bp + (size_t)d * 128 + lane * 4);
    float h0 = fmaxf(a.x + b.x, 0.f);
    float h1 = fmaxf(a.y + b.y, 0.f);
    float h2 = fmaxf(a.z + b.z, 0.f);
    float h3 = fmaxf(a.w + b.w, 0.f);
    float dot = h0 * s_w2[lane * 4] + h1 * s_w2[lane * 4 + 1]
              + h2 * s_w2[lane * 4 + 2] + h3 * s_w2[lane * 4 + 3];
    #pragma unroll
    for (int off = 16; off > 0; off >>= 1)
        dot += __shfl_xor_sync(0xFFFFFFFFu, dot, off);
    if (lane == 0) out[warp] = dot + __ldg(b2);
}

// ---------------- host launcher ----------------
static inline void zero_buf(float* p, long n_floats) {
    long n4 = n_floats / 4;
    int blocks = (int)((n4 + 255) / 256);
    if (blocks > 16384) blocks = 16384;
    zero4_kernel<<<blocks, 256>>>(reinterpret_cast<float4*>(p), n4);
}

extern "C" void kernel_launch(void* const* d_in, const int* in_sizes, int n_in,
                              void* d_out, int out_size) {
    const float* user_x    = (const float*)d_in[0];
    const float* book_x    = (const float*)d_in[1];
    const int*   edge_src  = (const int*)d_in[2];
    const int*   edge_dst  = (const int*)d_in[3];
    const int*   label_src = (const int*)d_in[4];
    const int*   label_dst = (const int*)d_in[5];
    const float* user_lin_w = (const float*)d_in[6];
    const float* user_lin_b = (const float*)d_in[7];
    const float* book_lin_w = (const float*)d_in[8];
    const float* book_lin_b = (const float*)d_in[9];
    const float* w1_ub_l = (const float*)d_in[10];
    const float* b1_ub   = (const float*)d_in[11];
    const float* w1_ub_r = (const float*)d_in[12];
    const float* w1_bu_l = (const float*)d_in[13];
    const float* b1_bu   = (const float*)d_in[14];
    const float* w1_bu_r = (const float*)d_in[15];
    const float* w2_ub_l = (const float*)d_in[16];
    const float* b2_ub   = (const float*)d_in[17];
    const float* w2_ub_r = (const float*)d_in[18];
    const float* w2_bu_l = (const float*)d_in[19];
    const float* b2_bu   = (const float*)d_in[20];
    const float* w2_bu_r = (const float*)d_in[21];
    const float* dec_w1  = (const float*)d_in[22];
    const float* dec_b1  = (const float*)d_in[23];
    const float* dec_w2  = (const float*)d_in[24];
    const float* dec_b2  = (const float*)d_in[25];

    int nu = in_sizes[0] / 3;
    int nb = in_sizes[1] / 384;
    int E  = in_sizes[2];
    int EL = in_sizes[4];
    float* out = (float*)d_out;

    float *u0, *b0, *u1, *b1, *u2, *b2, *uagg, *bagg, *ucnt, *bcnt, *up, *bp;
    cudaGetSymbolAddress((void**)&u0, g_u0);
    cudaGetSymbolAddress((void**)&b0, g_b0);
    cudaGetSymbolAddress((void**)&u1, g_u1);
    cudaGetSymbolAddress((void**)&b1, g_b1);
    cudaGetSymbolAddress((void**)&u2, g_u2);
    cudaGetSymbolAddress((void**)&b2, g_b2);
    cudaGetSymbolAddress((void**)&uagg, g_uagg);
    cudaGetSymbolAddress((void**)&bagg, g_bagg);
    cudaGetSymbolAddress((void**)&ucnt, g_ucnt);
    cudaGetSymbolAddress((void**)&bcnt, g_bcnt);
    cudaGetSymbolAddress((void**)&up, g_up);
    cudaGetSymbolAddress((void**)&bp, g_bp);

    // degree counts (reused by both layers)
    zero_buf(ucnt, nu);
    zero_buf(bcnt, nb);
    count_kernel<<<(E + 255) / 256, 256>>>(edge_src, edge_dst, ucnt, bcnt, E);

    // input projections
    {
        unsigned t = (unsigned)nu * 64u;
        user_proj_kernel<<<(t + 255) / 256, 256>>>(user_x, user_lin_w, user_lin_b, u0, nu);
    }
    book_proj_kernel<<<(nb + 7) / 8, 256>>>(book_x, book_lin_w, book_lin_b, b0, nb);

    unsigned agg_total = (unsigned)E * 16u;
    int agg_blocks = (int)((agg_total + 255u) / 256u);

    // ---- layer 1 ----
    zero_buf(bagg, (long)nb * 64);
    agg_kernel<<<agg_blocks, 256>>>(u0, edge_src, edge_dst, bagg, E);
    zero_buf(uagg, (long)nu * 64);
    agg_kernel<<<agg_blocks, 256>>>(b0, edge_dst, edge_src, uagg, E);
    sage_transform_kernel<true><<<(nb + 7) / 8, 256>>>(bagg, bcnt, b0, w1_ub_l, b1_ub, w1_ub_r, b1, nb);
    sage_transform_kernel<true><<<(nu + 7) / 8, 256>>>(uagg, ucnt, u0, w1_bu_l, b1_bu, w1_bu_r, u1, nu);

    // ---- layer 2 ----
    zero_buf(bagg, (long)nb * 64);
    agg_kernel<<<agg_blocks, 256>>>(u1, edge_src, edge_dst, bagg, E);
    zero_buf(uagg, (long)nu * 64);
    agg_kernel<<<agg_blocks, 256>>>(b1, edge_dst, edge_src, uagg, E);
    sage_transform_kernel<false><<<(nb + 7) / 8, 256>>>(bagg, bcnt, b1, w2_ub_l, b2_ub, w2_ub_r, b2, nb);
    sage_transform_kernel<false><<<(nu + 7) / 8, 256>>>(uagg, ucnt, u1, w2_bu_l, b2_bu, w2_bu_r, u2, nu);

    // ---- decoder: per-node partials, then per-edge combine ----
    dec_pre_kernel<<<(nu + 7) / 8, 256>>>(u2, dec_w1, dec_b1, up, nu);
    dec_pre_kernel<<<(nb + 7) / 8, 256>>>(b2, dec_w1 + 64 * 128, nullptr, bp, nb);

    int edge_blocks = (EL + 7) / 8;   // 8 warps/block, warp per edge
    dec_edge_kernel<<<edge_blocks, 256>>>(up, bp, label_src, label_dst, dec_w2, dec_b2, out, EL);
}

// round 2
// speedup vs baseline: 1.1835x; 1.1835x over previous
#include <cuda_runtime.h>
#include <cstdint>
#include <cstddef>

#define NU_MAX 100000
#define NB_MAX 50000
#define E_MAX  2000000
#define C 64
#define H 128

// ---------------- device scratch (static, allocation-free) -----------
__device__ float g_u0[NU_MAX * C];
__device__ float g_b0[NB_MAX * C];
__device__ float g_u1[NU_MAX * C];
__device__ float g_b1[NB_MAX * C];
__device__ float g_u2[NU_MAX * C];
__device__ float g_b2[NB_MAX * C];
__device__ float g_up[NU_MAX * H];
__device__ float g_bp[NB_MAX * H];
// CSR structures
__device__ int g_deg_u[NU_MAX];
__device__ int g_deg_b[NB_MAX];
__device__ int g_off_u[NU_MAX + 1];
__device__ int g_off_b[NB_MAX + 1];
__device__ int g_cur_u[NU_MAX];
__device__ int g_cur_b[NB_MAX];
__device__ int g_nbr_b_of_u[E_MAX];   // for each user, its book neighbors
__device__ int g_nbr_u_of_b[E_MAX];   // for each book, its user neighbors

// ---------------- utility ----------------
__global__ void zero_int_kernel(int* __restrict__ p, int n) {
    int i = blockIdx.x * blockDim.x + threadIdx.x;
    if (i < n) p[i] = 0;
}

__global__ void deg_kernel(const int* __restrict__ src, const int* __restrict__ dst,
                           int* __restrict__ degu, int* __restrict__ degb, int E) {
    int i = blockIdx.x * blockDim.x + threadIdx.x;
    if (i < E) {
        atomicAdd(degu + src[i], 1);
        atomicAdd(degb + dst[i], 1);
    }
}

// single block per side: block 0 scans user degrees, block 1 book degrees.
// writes exclusive offsets (n+1 entries) and a cursor copy.
__global__ void build_offsets_kernel(const int* __restrict__ degu, const int* __restrict__ degb,
                                     int* __restrict__ offu, int* __restrict__ offb,
                                     int* __restrict__ curu, int* __restrict__ curb,
                                     int nu, int nb) {
    const int* deg = (blockIdx.x == 0) ? degu : degb;
    int* off = (blockIdx.x == 0) ? offu : offb;
    int* cur = (blockIdx.x == 0) ? curu : curb;
    int n = (blockIdx.x == 0) ? nu : nb;
    __shared__ int s_warp[32];
    __shared__ int s_carry;
    int tid = threadIdx.x, lane = tid & 31, wid = tid >> 5;
    if (tid == 0) s_carry = 0;
    __syncthreads();
    for (int base = 0; base < n; base += 1024) {
        int i = base + tid;
        int v = (i < n) ? deg[i] : 0;
        int x = v;
        #pragma unroll
        for (int o = 1; o < 32; o <<= 1) {
            int t = __shfl_up_sync(0xFFFFFFFFu, x, o);
            if (lane >= o) x += t;
        }
        if (lane == 31) s_warp[wid] = x;
        __syncthreads();
        if (wid == 0) {
            int w = s_warp[lane];
            #pragma unroll
            for (int o = 1; o < 32; o <<= 1) {
                int t = __shfl_up_sync(0xFFFFFFFFu, w, o);
                if (lane >= o) w += t;
            }
            s_warp[lane] = w;
        }
        __syncthreads();
        int warpoff = (wid == 0) ? 0 : s_warp[wid - 1];
        int exc = s_carry + warpoff + x - v;
        if (i < n) { off[i] = exc; cur[i] = exc; }
        __syncthreads();
        if (tid == 0) s_carry += s_warp[31];
        __syncthreads();
    }
    if (tid == 0) off[n] = s_carry;
}

__global__ void scatter_kernel(const int* __restrict__ src, const int* __restrict__ dst,
                               int* __restrict__ curu, int* __restrict__ curb,
                               int* __restrict__ nbr_b_of_u, int* __restrict__ nbr_u_of_b,
                               int E) {
    int i = blockIdx.x * blockDim.x + threadIdx.x;
    if (i < E) {
        int s = src[i], d = dst[i];
        int pu = atomicAdd(curu + s, 1);
        nbr_b_of_u[pu] = d;
        int pb = atomicAdd(curb + d, 1);
        nbr_u_of_b[pb] = s;
    }
}

// ---------------- input projections ----------------
__global__ void user_proj_kernel(const float* __restrict__ x, const float* __restrict__ w,
                                 const float* __restrict__ b, float* __restrict__ out, int n) {
    unsigned i = blockIdx.x * blockDim.x + threadIdx.x;
    if (i >= (unsigned)n * 64u) return;
    unsigned node = i >> 6, j = i & 63u;
    const float* xr = x + (size_t)node * 3;
    float x0 = __ldg(xr), x1 = __ldg(xr + 1), x2 = __ldg(xr + 2);
    out[i] = __ldg(b + j) + x0 * __ldg(w + j) + x1 * __ldg(w + 64 + j) + x2 * __ldg(w + 128 + j);
}

__global__ void book_proj_kernel(const float* __restrict__ x, const float* __restrict__ w,
                                 const float* __restrict__ bias, float* __restrict__ out, int n) {
    __shared__ __align__(16) float s_w[96 * 64];
    __shared__ __align__(16) float s_row[8][384];
    int lane = threadIdx.x & 31, wid = threadIdx.x >> 5;
    int node = blockIdx.x * 8 + wid;
    bool valid = node < n;
    if (valid) {
        const float4* xr = reinterpret_cast<const float4*>(x + (size_t)node * 384);
        float4* sr = reinterpret_cast<float4*>(s_row[wid]);
        for (int i = lane; i < 96; i += 32) sr[i] = __ldg(xr + i);
    }
    float2 acc = make_float2(0.f, 0.f);
    if (valid) { acc.x = __ldg(bias + lane * 2); acc.y = __ldg(bias + lane * 2 + 1); }
    for (int ch = 0; ch < 4; ch++) {
        __syncthreads();
        const float2* wsrc = reinterpret_cast<const float2*>(w + ch * 96 * 64);
        float2* wd = reinterpret_cast<float2*>(s_w);
        for (int i = threadIdx.x; i < 96 * 64 / 2; i += 256) wd[i] = __ldg(wsrc + i);
        __syncthreads();
        if (valid) {
            #pragma unroll 8
            for (int kk = 0; kk < 96; kk++) {
                float xv = s_row[wid][ch * 96 + kk];
                float2 wv = *reinterpret_cast<const float2*>(s_w + kk * 64 + lane * 2);
                acc.x += xv * wv.x;
                acc.y += xv * wv.y;
            }
        }
    }
    if (valid)
        *reinterpret_cast<float2*>(out + (size_t)node * 64 + lane * 2) = acc;
}

// ---------------- fused SAGE: gather-aggregate + transform, warp per dst node ----------------
// out[node] = (mean_{s in nbr(node)} xsrc[s]) @ wl + b + xdst[node] @ wr [, relu]
template <bool RELU>
__global__ void sage_fused_kernel(const float* __restrict__ xsrc, const float* __restrict__ xdst,
                                  const int* __restrict__ offs, const int* __restrict__ nbr,
                                  const float* __restrict__ wl, const float* __restrict__ bias,
                                  const float* __restrict__ wr,
                                  float* __restrict__ out, int n) {
    __shared__ __align__(16) float s_wl[64 * 64];
    __shared__ __align__(16) float s_wr[64 * 64];
    __shared__ float s_b[64];
    __shared__ float s_rows[8][128];
    for (int i = threadIdx.x; i < 64 * 64; i += blockDim.x) { s_wl[i] = wl[i]; s_wr[i] = wr[i]; }
    if (threadIdx.x < 64) s_b[threadIdx.x] = bias[threadIdx.x];
    __syncthreads();
    int lane = threadIdx.x & 31, wid = threadIdx.x >> 5;
    int node = blockIdx.x * 8 + wid;
    if (node >= n) return;

    int beg = __ldg(offs + node);
    int end = __ldg(offs + node + 1);
    float accx = 0.f, accy = 0.f;
    int base = beg;
    // full batches of 32 edges
    for (; base + 32 <= end; base += 32) {
        int sidx = __ldg(nbr + base + lane);
        #pragma unroll
        for (int j = 0; j < 32; j++) {
            int s = __shfl_sync(0xFFFFFFFFu, sidx, j);
            float2 v = __ldg(reinterpret_cast<const float2*>(xsrc + (size_t)s * 64) + lane);
            accx += v.x; accy += v.y;
        }
    }
    // tail
    if (base < end) {
        int rem = end - base;
        int sidx = (lane < rem) ? __ldg(nbr + base + lane) : 0;
        for (int j = 0; j < rem; j++) {
            int s = __shfl_sync(0xFFFFFFFFu, sidx, j);
            float2 v = __ldg(reinterpret_cast<const float2*>(xsrc + (size_t)s * 64) + lane);
            accx += v.x; accy += v.y;
        }
    }
    float inv = 1.0f / fmaxf((float)(end - beg), 1.0f);
    float2 x = *reinterpret_cast<const float2*>(xdst + (size_t)node * 64 + lane * 2);
    s_rows[wid][lane * 2]     = accx * inv;
    s_rows[wid][lane * 2 + 1] = accy * inv;
    s_rows[wid][64 + lane * 2]     = x.x;
    s_rows[wid][64 + lane * 2 + 1] = x.y;
    __syncwarp();
    float2 acc = make_float2(s_b[lane * 2], s_b[lane * 2 + 1]);
    #pragma unroll 8
    for (int k = 0; k < 64; k++) {
        float mk = s_rows[wid][k];
        float xk = s_rows[wid][64 + k];
        float2 wlv = *reinterpret_cast<const float2*>(s_wl + k * 64 + lane * 2);
        float2 wrv = *reinterpret_cast<const float2*>(s_wr + k * 64 + lane * 2);
        acc.x += mk * wlv.x + xk * wrv.x;
        acc.y += mk * wlv.y + xk * wrv.y;
    }
    if (RELU) { acc.x = fmaxf(acc.x, 0.f); acc.y = fmaxf(acc.y, 0.f); }
    *reinterpret_cast<float2*>(out + (size_t)node * 64 + lane * 2) = acc;
}

// ---------------- decoder precompute: out[n,128] = x[n,64] @ w[64,128] (+bias) ----------------
__global__ void dec_pre_kernel(const float* __restrict__ x, const float* __restrict__ w,
                               const float* __restrict__ bias, float* __restrict__ out, int n) {
    __shared__ __align__(16) float s_w[64 * 128];
    __shared__ float s_rows[8][64];
    for (int i = threadIdx.x; i < 64 * 128; i += blockDim.x) s_w[i] = w[i];
    __syncthreads();
    int lane = threadIdx.x & 31, wid = threadIdx.x >> 5;
    int node = blockIdx.x * 8 + wid;
    if (node >= n) return;
    float2 xv = *reinterpret_cast<const float2*>(x + (size_t)node * 64 + lane * 2);
    s_rows[wid][lane * 2] = xv.x;
    s_rows[wid][lane * 2 + 1] = xv.y;
    __syncwarp();
    float4 acc;
    if (bias) acc = *reinterpret_cast<const float4*>(bias + lane * 4);
    else      acc = make_float4(0.f, 0.f, 0.f, 0.f);
    #pragma unroll 8
    for (int k = 0; k < 64; k++) {
        float xk = s_rows[wid][k];
        float4 wv = *reinterpret_cast<const float4*>(s_w + k * 128 + lane * 4);
        acc.x += xk * wv.x; acc.y += xk * wv.y; acc.z += xk * wv.z; acc.w += xk * wv.w;
    }
    *reinterpret_cast<float4*>(out + (size_t)node * 128 + lane * 4) = acc;
}

// ---------------- decoder edge kernel ----------------
__global__ void dec_edge_kernel(const float* __restrict__ Up, const float* __restrict__ Bp,
                                const int* __restrict__ ls, const int* __restrict__ ld,
                                const float* __restrict__ w2, const float* __restrict__ b2,
                                float* __restrict__ out, int m) {
    __shared__ float s_w2[128];
    if (threadIdx.x < 128) s_w2[threadIdx.x] = w2[threadIdx.x];
    __syncthreads();
    int warp = (blockIdx.x * blockDim.x + threadIdx.x) >> 5;
    int lane = threadIdx.x & 31;
    if (warp >= m) return;
    int s = __ldg(ls + warp);
    int d = __ldg(ld + warp);
    float4 a = *reinterpret_cast<const float4*>(Up + (size_t)s * 128 + lane * 4);
    float4 b = *reinterpret_cast<const float4*>(Bp + (size_t)d * 128 + lane * 4);
    float h0 = fmaxf(a.x + b.x, 0.f);
    float h1 = fmaxf(a.y + b.y, 0.f);
    float h2 = fmaxf(a.z + b.z, 0.f);
    float h3 = fmaxf(a.w + b.w, 0.f);
    float dot = h0 * s_w2[lane * 4] + h1 * s_w2[lane * 4 + 1]
              + h2 * s_w2[lane * 4 + 2] + h3 * s_w2[lane * 4 + 3];
    #pragma unroll
    for (int off = 16; off > 0; off >>= 1)
        dot += __shfl_xor_sync(0xFFFFFFFFu, dot, off);
    if (lane == 0) out[warp] = dot + __ldg(b2);
}

// ---------------- host launcher ----------------
extern "C" void kernel_launch(void* const* d_in, const int* in_sizes, int n_in,
                              void* d_out, int out_size) {
    const float* user_x    = (const float*)d_in[0];
    const float* book_x    = (const float*)d_in[1];
    const int*   edge_src  = (const int*)d_in[2];
    const int*   edge_dst  = (const int*)d_in[3];
    const int*   label_src = (const int*)d_in[4];
    const int*   label_dst = (const int*)d_in[5];
    const float* user_lin_w = (const float*)d_in[6];
    const float* user_lin_b = (const float*)d_in[7];
    const float* book_lin_w = (const float*)d_in[8];
    const float* book_lin_b = (const float*)d_in[9];
    const float* w1_ub_l = (const float*)d_in[10];
    const float* b1_ub   = (const float*)d_in[11];
    const float* w1_ub_r = (const float*)d_in[12];
    const float* w1_bu_l = (const float*)d_in[13];
    const float* b1_bu   = (const float*)d_in[14];
    const float* w1_bu_r = (const float*)d_in[15];
    const float* w2_ub_l = (const float*)d_in[16];
    const float* b2_ub   = (const float*)d_in[17];
    const float* w2_ub_r = (const float*)d_in[18];
    const float* w2_bu_l = (const float*)d_in[19];
    const float* b2_bu   = (const float*)d_in[20];
    const float* w2_bu_r = (const float*)d_in[21];
    const float* dec_w1  = (const float*)d_in[22];
    const float* dec_b1  = (const float*)d_in[23];
    const float* dec_w2  = (const float*)d_in[24];
    const float* dec_b2  = (const float*)d_in[25];

    int nu = in_sizes[0] / 3;
    int nb = in_sizes[1] / 384;
    int E  = in_sizes[2];
    int EL = in_sizes[4];
    float* out = (float*)d_out;

    float *u0, *b0, *u1, *b1, *u2, *b2, *up, *bp;
    int *degu, *degb, *offu, *offb, *curu, *curb, *nbu, *nub;
    cudaGetSymbolAddress((void**)&u0, g_u0);
    cudaGetSymbolAddress((void**)&b0, g_b0);
    cudaGetSymbolAddress((void**)&u1, g_u1);
    cudaGetSymbolAddress((void**)&b1, g_b1);
    cudaGetSymbolAddress((void**)&u2, g_u2);
    cudaGetSymbolAddress((void**)&b2, g_b2);
    cudaGetSymbolAddress((void**)&up, g_up);
    cudaGetSymbolAddress((void**)&bp, g_bp);
    cudaGetSymbolAddress((void**)&degu, g_deg_u);
    cudaGetSymbolAddress((void**)&degb, g_deg_b);
    cudaGetSymbolAddress((void**)&offu, g_off_u);
    cudaGetSymbolAddress((void**)&offb, g_off_b);
    cudaGetSymbolAddress((void**)&curu, g_cur_u);
    cudaGetSymbolAddress((void**)&curb, g_cur_b);
    cudaGetSymbolAddress((void**)&nbu, g_nbr_b_of_u);
    cudaGetSymbolAddress((void**)&nub, g_nbr_u_of_b);

    // ---- CSR build ----
    zero_int_kernel<<<(nu + 255) / 256, 256>>>(degu, nu);
    zero_int_kernel<<<(nb + 255) / 256, 256>>>(degb, nb);
    deg_kernel<<<(E + 255) / 256, 256>>>(edge_src, edge_dst, degu, degb, E);
    build_offsets_kernel<<<2, 1024>>>(degu, degb, offu, offb, curu, curb, nu, nb);
    scatter_kernel<<<(E + 255) / 256, 256>>>(edge_src, edge_dst, curu, curb, nbu, nub, E);

    // ---- input projections (overlap with CSR build on same stream order) ----
    {
        unsigned t = (unsigned)nu * 64u;
        user_proj_kernel<<<(t + 255) / 256, 256>>>(user_x, user_lin_w, user_lin_b, u0, nu);
    }
    book_proj_kernel<<<(nb + 7) / 8, 256>>>(book_x, book_lin_w, book_lin_b, b0, nb);

    // ---- layer 1 (fused gather+transform, relu) ----
    sage_fused_kernel<true><<<(nb + 7) / 8, 256>>>(u0, b0, offb, nub, w1_ub_l, b1_ub, w1_ub_r, b1, nb);
    sage_fused_kernel<true><<<(nu + 7) / 8, 256>>>(b0, u0, offu, nbu, w1_bu_l, b1_bu, w1_bu_r, u1, nu);

    // ---- layer 2 (no relu) ----
    sage_fused_kernel<false><<<(nb + 7) / 8, 256>>>(u1, b1, offb, nub, w2_ub_l, b2_ub, w2_ub_r, b2, nb);
    sage_fused_kernel<false><<<(nu + 7) / 8, 256>>>(b1, u1, offu, nbu, w2_bu_l, b2_bu, w2_bu_r, u2, nu);

    // ---- decoder ----
    dec_pre_kernel<<<(nu + 7) / 8, 256>>>(u2, dec_w1, dec_b1, up, nu);
    dec_pre_kernel<<<(nb + 7) / 8, 256>>>(b2, dec_w1 + 64 * 128, nullptr, bp, nb);
    dec_edge_kernel<<<(EL + 7) / 8, 256>>>(up, bp, label_src, label_dst, dec_w2, dec_b2, out, EL);
}

// round 3
// speedup vs baseline: 1.3185x; 1.1140x over previous
#include <cuda_runtime.h>
#include <cstdint>
#include <cstddef>

#define NU_MAX 100000
#define NB_MAX 50000
#define E_MAX  2000000
#define C 64
#define H 128

// ---------------- device scratch (static, allocation-free) -----------
__device__ float g_u0[NU_MAX * C];
__device__ float g_b0[NB_MAX * C];
__device__ float g_u1[NU_MAX * C];
__device__ float g_b1[NB_MAX * C];
__device__ float g_u2[NU_MAX * C];
__device__ float g_b2[NB_MAX * C];
__device__ float g_up[NU_MAX * H];
__device__ float g_bp[NB_MAX * H];
// CSR structures
__device__ int g_deg_u[NU_MAX];
__device__ int g_deg_b[NB_MAX];
__device__ int g_off_u[NU_MAX];
__device__ int g_off_b[NB_MAX];
__device__ int g_cur_u[NU_MAX];
__device__ int g_cur_b[NB_MAX];
__device__ int g_nbr_b_of_u[E_MAX];
__device__ int g_nbr_u_of_b[E_MAX];
__device__ int g_counters[2];

// ---------------- utility ----------------
__global__ void zero_int_kernel(int* __restrict__ p, int n) {
    int i = blockIdx.x * blockDim.x + threadIdx.x;
    if (i < n) p[i] = 0;
}

__global__ void deg_kernel(const int* __restrict__ src, const int* __restrict__ dst,
                           int* __restrict__ degu, int* __restrict__ degb, int E) {
    int i = blockIdx.x * blockDim.x + threadIdx.x;
    if (i < E) {
        atomicAdd(degu + src[i], 1);
        atomicAdd(degb + dst[i], 1);
    }
}

// parallel segment allocation: block-local exclusive scan + atomic base grab.
// segment order is arbitrary but each node gets a private [off, off+deg) range.
__global__ void alloc_offsets_kernel(const int* __restrict__ deg, int* __restrict__ off,
                                     int* __restrict__ cur, int* __restrict__ counter, int n) {
    __shared__ int s_warp[32];
    __shared__ int s_base;
    int tid = threadIdx.x, lane = tid & 31, wid = tid >> 5;
    int i = blockIdx.x * 1024 + tid;
    int v = (i < n) ? deg[i] : 0;
    int x = v;
    #pragma unroll
    for (int o = 1; o < 32; o <<= 1) {
        int t = __shfl_up_sync(0xFFFFFFFFu, x, o);
        if (lane >= o) x += t;
    }
    if (lane == 31) s_warp[wid] = x;
    __syncthreads();
    if (wid == 0) {
        int w = s_warp[lane];
        #pragma unroll
        for (int o = 1; o < 32; o <<= 1) {
            int t = __shfl_up_sync(0xFFFFFFFFu, w, o);
            if (lane >= o) w += t;
        }
        s_warp[lane] = w;
    }
    __syncthreads();
    if (tid == 0) s_base = atomicAdd(counter, s_warp[31]);
    __syncthreads();
    int warpoff = (wid == 0) ? 0 : s_warp[wid - 1];
    int exc = s_base + warpoff + x - v;
    if (i < n) { off[i] = exc; cur[i] = exc; }
}

__global__ void scatter_kernel(const int* __restrict__ src, const int* __restrict__ dst,
                               int* __restrict__ curu, int* __restrict__ curb,
                               int* __restrict__ nbr_b_of_u, int* __restrict__ nbr_u_of_b,
                               int E) {
    int i = blockIdx.x * blockDim.x + threadIdx.x;
    if (i < E) {
        int s = src[i], d = dst[i];
        int pu = atomicAdd(curu + s, 1);
        nbr_b_of_u[pu] = d;
        int pb = atomicAdd(curb + d, 1);
        nbr_u_of_b[pb] = s;
    }
}

// ---------------- input projections ----------------
// thread produces 4 output channels: n*16 threads total
__global__ void user_proj_kernel(const float* __restrict__ x, const float* __restrict__ w,
                                 const float* __restrict__ b, float* __restrict__ out, int n) {
    unsigned i = blockIdx.x * blockDim.x + threadIdx.x;
    if (i >= (unsigned)n * 16u) return;
    unsigned node = i >> 4, j4 = (i & 15u) * 4;
    const float* xr = x + (size_t)node * 3;
    float x0 = __ldg(xr), x1 = __ldg(xr + 1), x2 = __ldg(xr + 2);
    float4 bb = __ldg(reinterpret_cast<const float4*>(b + j4));
    float4 w0 = __ldg(reinterpret_cast<const float4*>(w + j4));
    float4 w1 = __ldg(reinterpret_cast<const float4*>(w + 64 + j4));
    float4 w2 = __ldg(reinterpret_cast<const float4*>(w + 128 + j4));
    float4 r;
    r.x = bb.x + x0 * w0.x + x1 * w1.x + x2 * w2.x;
    r.y = bb.y + x0 * w0.y + x1 * w1.y + x2 * w2.y;
    r.z = bb.z + x0 * w0.z + x1 * w1.z + x2 * w2.z;
    r.w = bb.w + x0 * w0.w + x1 * w1.w + x2 * w2.w;
    *reinterpret_cast<float4*>(out + (size_t)node * 64 + j4) = r;
}

// book: [n,384] @ [384,64] + b. Full weights resident in dynamic smem (96KB),
// grid-stride over node groups of 32 (8 warps x 4 rows), per-warp row staging.
__global__ void book_proj_kernel(const float* __restrict__ x, const float* __restrict__ w,
                                 const float* __restrict__ bias, float* __restrict__ out, int n) {
    extern __shared__ float dsm[];
    float* s_w = dsm;                 // 384*64 floats
    float* s_rc = dsm + 384 * 64;     // 32 rows x 96 chunk floats
    int tid = threadIdx.x, lane = tid & 31, wid = tid >> 5;
    // load full weight matrix once per block
    const float4* wsrc = reinterpret_cast<const float4*>(w);
    float4* wdst = reinterpret_cast<float4*>(s_w);
    for (int i = tid; i < 384 * 64 / 4; i += 256) wdst[i] = __ldg(wsrc + i);
    float2 bb = make_float2(__ldg(bias + lane * 2), __ldg(bias + lane * 2 + 1));
    __syncthreads();

    for (int g = blockIdx.x * 32; g < n; g += gridDim.x * 32) {
        int node0 = g + wid * 4;
        float2 acc[4];
        #pragma unroll
        for (int r = 0; r < 4; r++) acc[r] = bb;
        for (int ch = 0; ch < 4; ch++) {
            // stage this chunk's 4 rows (private to this warp)
            #pragma unroll
            for (int r = 0; r < 4; r++) {
                int nd = node0 + r;
                if (nd < n) {
                    const float* xr = x + (size_t)nd * 384 + ch * 96;
                    float* dst = s_rc + (wid * 4 + r) * 96;
                    dst[lane] = __ldg(xr + lane);
                    dst[lane + 32] = __ldg(xr + lane + 32);
                    dst[lane + 64] = __ldg(xr + lane + 64);
                }
            }
            __syncwarp();
            const float* wch = s_w + ch * 96 * 64;
            #pragma unroll 8
            for (int k = 0; k < 96; k++) {
                float2 wv = *reinterpret_cast<const float2*>(wch + k * 64 + lane * 2);
                #pragma unroll
                for (int r = 0; r < 4; r++) {
                    float xv = s_rc[(wid * 4 + r) * 96 + k];
                    acc[r].x += xv * wv.x;
                    acc[r].y += xv * wv.y;
                }
            }
            __syncwarp();
        }
        #pragma unroll
        for (int r = 0; r < 4; r++) {
            int nd = node0 + r;
            if (nd < n)
                *reinterpret_cast<float2*>(out + (size_t)nd * 64 + lane * 2) = acc[r];
        }
    }
}

// ---------------- fused SAGE: gather-aggregate + transform, warp per dst node ----------------
template <bool RELU>
__global__ void sage_fused_kernel(const float* __restrict__ xsrc, const float* __restrict__ xdst,
                                  const int* __restrict__ offs, const int* __restrict__ degs,
                                  const int* __restrict__ nbr,
                                  const float* __restrict__ wl, const float* __restrict__ bias,
                                  const float* __restrict__ wr,
                                  float* __restrict__ out, int n) {
    __shared__ __align__(16) float s_wl[64 * 64];
    __shared__ __align__(16) float s_wr[64 * 64];
    __shared__ float s_b[64];
    __shared__ float s_rows[8][128];
    for (int i = threadIdx.x; i < 64 * 64; i += blockDim.x) { s_wl[i] = wl[i]; s_wr[i] = wr[i]; }
    if (threadIdx.x < 64) s_b[threadIdx.x] = bias[threadIdx.x];
    __syncthreads();
    int lane = threadIdx.x & 31, wid = threadIdx.x >> 5;

    for (int node = blockIdx.x * 8 + wid; node < n; node += gridDim.x * 8) {
        int beg = __ldg(offs + node);
        int dg = __ldg(degs + node);
        int end = beg + dg;
        float accx = 0.f, accy = 0.f;
        int base = beg;
        for (; base + 32 <= end; base += 32) {
            int sidx = __ldg(nbr + base + lane);
            #pragma unroll
            for (int j = 0; j < 32; j++) {
                int s = __shfl_sync(0xFFFFFFFFu, sidx, j);
                float2 v = __ldg(reinterpret_cast<const float2*>(xsrc + (size_t)s * 64) + lane);
                accx += v.x; accy += v.y;
            }
        }
        if (base < end) {
            int rem = end - base;
            int sidx = (lane < rem) ? __ldg(nbr + base + lane) : 0;
            for (int j = 0; j < rem; j++) {
                int s = __shfl_sync(0xFFFFFFFFu, sidx, j);
                float2 v = __ldg(reinterpret_cast<const float2*>(xsrc + (size_t)s * 64) + lane);
                accx += v.x; accy += v.y;
            }
        }
        float inv = 1.0f / fmaxf((float)dg, 1.0f);
        float2 x = *reinterpret_cast<const float2*>(xdst + (size_t)node * 64 + lane * 2);
        s_rows[wid][lane * 2]     = accx * inv;
        s_rows[wid][lane * 2 + 1] = accy * inv;
        s_rows[wid][64 + lane * 2]     = x.x;
        s_rows[wid][64 + lane * 2 + 1] = x.y;
        __syncwarp();
        float2 acc = make_float2(s_b[lane * 2], s_b[lane * 2 + 1]);
        #pragma unroll 8
        for (int k = 0; k < 64; k++) {
            float mk = s_rows[wid][k];
            float xk = s_rows[wid][64 + k];
            float2 wlv = *reinterpret_cast<const float2*>(s_wl + k * 64 + lane * 2);
            float2 wrv = *reinterpret_cast<const float2*>(s_wr + k * 64 + lane * 2);
            acc.x += mk * wlv.x + xk * wrv.x;
            acc.y += mk * wlv.y + xk * wrv.y;
        }
        if (RELU) { acc.x = fmaxf(acc.x, 0.f); acc.y = fmaxf(acc.y, 0.f); }
        *reinterpret_cast<float2*>(out + (size_t)node * 64 + lane * 2) = acc;
        __syncwarp();
    }
}

// ---------------- decoder precompute: out[n,128] = x[n,64] @ w[64,128] (+bias) ----------------
__global__ void dec_pre_kernel(const float* __restrict__ x, const float* __restrict__ w,
                               const float* __restrict__ bias, float* __restrict__ out, int n) {
    __shared__ __align__(16) float s_w[64 * 128];
    __shared__ float s_rows[8][64];
    for (int i = threadIdx.x; i < 64 * 128; i += blockDim.x) s_w[i] = w[i];
    __syncthreads();
    int lane = threadIdx.x & 31, wid = threadIdx.x >> 5;
    for (int node = blockIdx.x * 8 + wid; node < n; node += gridDim.x * 8) {
        float2 xv = *reinterpret_cast<const float2*>(x + (size_t)node * 64 + lane * 2);
        s_rows[wid][lane * 2] = xv.x;
        s_rows[wid][lane * 2 + 1] = xv.y;
        __syncwarp();
        float4 acc;
        if (bias) acc = *reinterpret_cast<const float4*>(bias + lane * 4);
        else      acc = make_float4(0.f, 0.f, 0.f, 0.f);
        #pragma unroll 8
        for (int k = 0; k < 64; k++) {
            float xk = s_rows[wid][k];
            float4 wv = *reinterpret_cast<const float4*>(s_w + k * 128 + lane * 4);
            acc.x += xk * wv.x; acc.y += xk * wv.y; acc.z += xk * wv.z; acc.w += xk * wv.w;
        }
        *reinterpret_cast<float4*>(out + (size_t)node * 128 + lane * 4) = acc;
        __syncwarp();
    }
}

// ---------------- decoder edge kernel ----------------
__global__ void dec_edge_kernel(const float* __restrict__ Up, const float* __restrict__ Bp,
                                const int* __restrict__ ls, const int* __restrict__ ld,
                                const float* __restrict__ w2, const float* __restrict__ b2,
                                float* __restrict__ out, int m) {
    __shared__ float s_w2[128];
    if (threadIdx.x < 128) s_w2[threadIdx.x] = w2[threadIdx.x];
    __syncthreads();
    int warp = (blockIdx.x * blockDim.x + threadIdx.x) >> 5;
    int lane = threadIdx.x & 31;
    if (warp >= m) return;
    int s = __ldg(ls + warp);
    int d = __ldg(ld + warp);
    float4 a = *reinterpret_cast<const float4*>(Up + (size_t)s * 128 + lane * 4);
    float4 b = *reinterpret_cast<const float4*>(Bp + (size_t)d * 128 + lane * 4);
    float h0 = fmaxf(a.x + b.x, 0.f);
    float h1 = fmaxf(a.y + b.y, 0.f);
    float h2 = fmaxf(a.z + b.z, 0.f);
    float h3 = fmaxf(a.w + b.w, 0.f);
    float dot = h0 * s_w2[lane * 4] + h1 * s_w2[lane * 4 + 1]
              + h2 * s_w2[lane * 4 + 2] + h3 * s_w2[lane * 4 + 3];
    #pragma unroll
    for (int off = 16; off > 0; off >>= 1)
        dot += __shfl_xor_sync(0xFFFFFFFFu, dot, off);
    if (lane == 0) out[warp] = dot + __ldg(b2);
}

// ---------------- host launcher ----------------
extern "C" void kernel_launch(void* const* d_in, const int* in_sizes, int n_in,
                              void* d_out, int out_size) {
    const float* user_x    = (const float*)d_in[0];
    const float* book_x    = (const float*)d_in[1];
    const int*   edge_src  = (const int*)d_in[2];
    const int*   edge_dst  = (const int*)d_in[3];
    const int*   label_src = (const int*)d_in[4];
    const int*   label_dst = (const int*)d_in[5];
    const float* user_lin_w = (const float*)d_in[6];
    const float* user_lin_b = (const float*)d_in[7];
    const float* book_lin_w = (const float*)d_in[8];
    const float* book_lin_b = (const float*)d_in[9];
    const float* w1_ub_l = (const float*)d_in[10];
    const float* b1_ub   = (const float*)d_in[11];
    const float* w1_ub_r = (const float*)d_in[12];
    const float* w1_bu_l = (const float*)d_in[13];
    const float* b1_bu   = (const float*)d_in[14];
    const float* w1_bu_r = (const float*)d_in[15];
    const float* w2_ub_l = (const float*)d_in[16];
    const float* b2_ub   = (const float*)d_in[17];
    const float* w2_ub_r = (const float*)d_in[18];
    const float* w2_bu_l = (const float*)d_in[19];
    const float* b2_bu   = (const float*)d_in[20];
    const float* w2_bu_r = (const float*)d_in[21];
    const float* dec_w1  = (const float*)d_in[22];
    const float* dec_b1  = (const float*)d_in[23];
    const float* dec_w2  = (const float*)d_in[24];
    const float* dec_b2  = (const float*)d_in[25];

    int nu = in_sizes[0] / 3;
    int nb = in_sizes[1] / 384;
    int E  = in_sizes[2];
    int EL = in_sizes[4];
    float* out = (float*)d_out;

    float *u0, *b0, *u1, *b1, *u2, *b2, *up, *bp;
    int *degu, *degb, *offu, *offb, *curu, *curb, *nbu, *nub, *cnts;
    cudaGetSymbolAddress((void**)&u0, g_u0);
    cudaGetSymbolAddress((void**)&b0, g_b0);
    cudaGetSymbolAddress((void**)&u1, g_u1);
    cudaGetSymbolAddress((void**)&b1, g_b1);
    cudaGetSymbolAddress((void**)&u2, g_u2);
    cudaGetSymbolAddress((void**)&b2, g_b2);
    cudaGetSymbolAddress((void**)&up, g_up);
    cudaGetSymbolAddress((void**)&bp, g_bp);
    cudaGetSymbolAddress((void**)&degu, g_deg_u);
    cudaGetSymbolAddress((void**)&degb, g_deg_b);
    cudaGetSymbolAddress((void**)&offu, g_off_u);
    cudaGetSymbolAddress((void**)&offb, g_off_b);
    cudaGetSymbolAddress((void**)&curu, g_cur_u);
    cudaGetSymbolAddress((void**)&curb, g_cur_b);
    cudaGetSymbolAddress((void**)&nbu, g_nbr_b_of_u);
    cudaGetSymbolAddress((void**)&nub, g_nbr_u_of_b);
    cudaGetSymbolAddress((void**)&cnts, g_counters);

    // allow 110.6KB dynamic smem for book_proj (full-weight resident)
    static const int BOOK_SMEM = (384 * 64 + 32 * 96) * 4;
    cudaFuncSetAttribute(book_proj_kernel, cudaFuncAttributeMaxDynamicSharedMemorySize, BOOK_SMEM);

    // ---- CSR build ----
    zero_int_kernel<<<(nu + 255) / 256, 256>>>(degu, nu);
    zero_int_kernel<<<(nb + 255) / 256, 256>>>(degb, nb);
    zero_int_kernel<<<1, 32>>>(cnts, 2);
    deg_kernel<<<(E + 255) / 256, 256>>>(edge_src, edge_dst, degu, degb, E);
    alloc_offsets_kernel<<<(nu + 1023) / 1024, 1024>>>(degu, offu, curu, cnts + 0, nu);
    alloc_offsets_kernel<<<(nb + 1023) / 1024, 1024>>>(degb, offb, curb, cnts + 1, nb);
    scatter_kernel<<<(E + 255) / 256, 256>>>(edge_src, edge_dst, curu, curb, nbu, nub, E);

    // ---- input projections ----
    {
        unsigned t = (unsigned)nu * 16u;
        user_proj_kernel<<<(t + 255) / 256, 256>>>(user_x, user_lin_w, user_lin_b, u0, nu);
    }
    book_proj_kernel<<<296, 256, BOOK_SMEM>>>(book_x, book_lin_w, book_lin_b, b0, nb);

    // ---- layer 1 (fused gather+transform, relu) ----
    sage_fused_kernel<true><<<1024, 256>>>(u0, b0, offb, degb, nub, w1_ub_l, b1_ub, w1_ub_r, b1, nb);
    sage_fused_kernel<true><<<1024, 256>>>(b0, u0, offu, degu, nbu, w1_bu_l, b1_bu, w1_bu_r, u1, nu);

    // ---- layer 2 (no relu) ----
    sage_fused_kernel<false><<<1024, 256>>>(u1, b1, offb, degb, nub, w2_ub_l, b2_ub, w2_ub_r, b2, nb);
    sage_fused_kernel<false><<<1024, 256>>>(b1, u1, offu, degu, nbu, w2_bu_l, b2_bu, w2_bu_r, u2, nu);

    // ---- decoder ----
    dec_pre_kernel<<<768, 256>>>(u2, dec_w1, dec_b1, up, nu);
    dec_pre_kernel<<<768, 256>>>(b2, dec_w1 + 64 * 128, nullptr, bp, nb);
    dec_edge_kernel<<<(EL + 7) / 8, 256>>>(up, bp, label_src, label_dst, dec_w2, dec_b2, out, EL);
}

// round 4
// speedup vs baseline: 1.4319x; 1.0860x over previous
#include <cuda_runtime.h>
#include <cstdint>
#include <cstddef>

#define NU_MAX 100000
#define NB_MAX 50000
#define E_MAX  2000000
#define C 64
#define H 128

// ---------------- device scratch (static, allocation-free) -----------
__device__ float g_u0[NU_MAX * C];
__device__ float g_b0[NB_MAX * C];
__device__ float g_u1[NU_MAX * C];
__device__ float g_b1[NB_MAX * C];
__device__ float g_u2[NU_MAX * C];
__device__ float g_b2[NB_MAX * C];
__device__ float g_up[NU_MAX * H];
__device__ float g_bp[NB_MAX * H];
// CSR structures
__device__ int g_deg_u[NU_MAX];
__device__ int g_deg_b[NB_MAX];
__device__ int g_off_u[NU_MAX];
__device__ int g_off_b[NB_MAX];
__device__ int g_cur_u[NU_MAX];
__device__ int g_cur_b[NB_MAX];
__device__ int g_nbr_b_of_u[E_MAX];
__device__ int g_nbr_u_of_b[E_MAX];
__device__ int g_counters[2];

// ---------------- utility ----------------
__global__ void zero_all_kernel(int* __restrict__ a, int na,
                                int* __restrict__ b, int nb_,
                                int* __restrict__ c, int nc) {
    int i = blockIdx.x * blockDim.x + threadIdx.x;
    if (i < na) a[i] = 0;
    if (i < nb_) b[i] = 0;
    if (i < nc) c[i] = 0;
}

__global__ void deg_kernel(const int* __restrict__ src, const int* __restrict__ dst,
                           int* __restrict__ degu, int* __restrict__ degb, int E) {
    int i = (blockIdx.x * blockDim.x + threadIdx.x) * 2;
    if (i + 1 < E) {
        int s0 = __ldg(src + i), s1 = __ldg(src + i + 1);
        int d0 = __ldg(dst + i), d1 = __ldg(dst + i + 1);
        atomicAdd(degu + s0, 1);
        atomicAdd(degu + s1, 1);
        atomicAdd(degb + d0, 1);
        atomicAdd(degb + d1, 1);
    } else if (i < E) {
        atomicAdd(degu + __ldg(src + i), 1);
        atomicAdd(degb + __ldg(dst + i), 1);
    }
}

// parallel segment allocation: block-local exclusive scan + atomic base grab.
__global__ void alloc_offsets_kernel(const int* __restrict__ deg, int* __restrict__ off,
                                     int* __restrict__ cur, int* __restrict__ counter, int n) {
    __shared__ int s_warp[32];
    __shared__ int s_base;
    int tid = threadIdx.x, lane = tid & 31, wid = tid >> 5;
    int i = blockIdx.x * 1024 + tid;
    int v = (i < n) ? deg[i] : 0;
    int x = v;
    #pragma unroll
    for (int o = 1; o < 32; o <<= 1) {
        int t = __shfl_up_sync(0xFFFFFFFFu, x, o);
        if (lane >= o) x += t;
    }
    if (lane == 31) s_warp[wid] = x;
    __syncthreads();
    if (wid == 0) {
        int w = s_warp[lane];
        #pragma unroll
        for (int o = 1; o < 32; o <<= 1) {
            int t = __shfl_up_sync(0xFFFFFFFFu, w, o);
            if (lane >= o) w += t;
        }
        s_warp[lane] = w;
    }
    __syncthreads();
    if (tid == 0) s_base = atomicAdd(counter, s_warp[31]);
    __syncthreads();
    int warpoff = (wid == 0) ? 0 : s_warp[wid - 1];
    int exc = s_base + warpoff + x - v;
    if (i < n) { off[i] = exc; cur[i] = exc; }
}

__global__ void scatter_kernel(const int* __restrict__ src, const int* __restrict__ dst,
                               int* __restrict__ curu, int* __restrict__ curb,
                               int* __restrict__ nbr_b_of_u, int* __restrict__ nbr_u_of_b,
                               int E) {
    int i = blockIdx.x * blockDim.x + threadIdx.x;
    if (i < E) {
        int s = src[i], d = dst[i];
        int pu = atomicAdd(curu + s, 1);
        nbr_b_of_u[pu] = d;
        int pb = atomicAdd(curb + d, 1);
        nbr_u_of_b[pb] = s;
    }
}

// ---------------- input projections ----------------
__global__ void user_proj_kernel(const float* __restrict__ x, const float* __restrict__ w,
                                 const float* __restrict__ b, float* __restrict__ out, int n) {
    unsigned i = blockIdx.x * blockDim.x + threadIdx.x;
    if (i >= (unsigned)n * 16u) return;
    unsigned node = i >> 4, j4 = (i & 15u) * 4;
    const float* xr = x + (size_t)node * 3;
    float x0 = __ldg(xr), x1 = __ldg(xr + 1), x2 = __ldg(xr + 2);
    float4 bb = __ldg(reinterpret_cast<const float4*>(b + j4));
    float4 w0 = __ldg(reinterpret_cast<const float4*>(w + j4));
    float4 w1 = __ldg(reinterpret_cast<const float4*>(w + 64 + j4));
    float4 w2 = __ldg(reinterpret_cast<const float4*>(w + 128 + j4));
    float4 r;
    r.x = bb.x + x0 * w0.x + x1 * w1.x + x2 * w2.x;
    r.y = bb.y + x0 * w0.y + x1 * w1.y + x2 * w2.y;
    r.z = bb.z + x0 * w0.z + x1 * w1.z + x2 * w2.z;
    r.w = bb.w + x0 * w0.w + x1 * w1.w + x2 * w2.w;
    *reinterpret_cast<float4*>(out + (size_t)node * 64 + j4) = r;
}

// book: [n,384] @ [384,64] + b, full weights in dynamic smem, grid-stride.
__global__ void book_proj_kernel(const float* __restrict__ x, const float* __restrict__ w,
                                 const float* __restrict__ bias, float* __restrict__ out, int n) {
    extern __shared__ float dsm[];
    float* s_w = dsm;                 // 384*64
    float* s_rc = dsm + 384 * 64;     // 32 rows x 96
    int tid = threadIdx.x, lane = tid & 31, wid = tid >> 5;
    const float4* wsrc = reinterpret_cast<const float4*>(w);
    float4* wdst = reinterpret_cast<float4*>(s_w);
    for (int i = tid; i < 384 * 64 / 4; i += 256) wdst[i] = __ldg(wsrc + i);
    float2 bb = make_float2(__ldg(bias + lane * 2), __ldg(bias + lane * 2 + 1));
    __syncthreads();

    for (int g = blockIdx.x * 32; g < n; g += gridDim.x * 32) {
        int node0 = g + wid * 4;
        float2 acc[4];
        #pragma unroll
        for (int r = 0; r < 4; r++) acc[r] = bb;
        for (int ch = 0; ch < 4; ch++) {
            #pragma unroll
            for (int r = 0; r < 4; r++) {
                int nd = node0 + r;
                if (nd < n) {
                    const float* xr = x + (size_t)nd * 384 + ch * 96;
                    float* dst = s_rc + (wid * 4 + r) * 96;
                    dst[lane] = __ldg(xr + lane);
                    dst[lane + 32] = __ldg(xr + lane + 32);
                    dst[lane + 64] = __ldg(xr + lane + 64);
                }
            }
            __syncwarp();
            const float* wch = s_w + ch * 96 * 64;
            #pragma unroll 8
            for (int k = 0; k < 96; k++) {
                float2 wv = *reinterpret_cast<const float2*>(wch + k * 64 + lane * 2);
                #pragma unroll
                for (int r = 0; r < 4; r++) {
                    float xv = s_rc[(wid * 4 + r) * 96 + k];
                    acc[r].x += xv * wv.x;
                    acc[r].y += xv * wv.y;
                }
            }
            __syncwarp();
        }
        #pragma unroll
        for (int r = 0; r < 4; r++) {
            int nd = node0 + r;
            if (nd < n)
                *reinterpret_cast<float2*>(out + (size_t)nd * 64 + lane * 2) = acc[r];
        }
    }
}

// ---------------- fused SAGE: gather-aggregate + transform, warp per dst node --------
template <bool RELU>
__global__ void __launch_bounds__(256)
sage_fused_kernel(const float* __restrict__ xsrc, const float* __restrict__ xdst,
                  const int* __restrict__ offs, const int* __restrict__ degs,
                  const int* __restrict__ nbr,
                  const float* __restrict__ wl, const float* __restrict__ bias,
                  const float* __restrict__ wr,
                  float* __restrict__ out, int n) {
    __shared__ __align__(16) float s_wl[64 * 64];
    __shared__ __align__(16) float s_wr[64 * 64];
    __shared__ float s_b[64];
    __shared__ float s_rows[8][128];
    for (int i = threadIdx.x; i < 64 * 64; i += blockDim.x) { s_wl[i] = wl[i]; s_wr[i] = wr[i]; }
    if (threadIdx.x < 64) s_b[threadIdx.x] = bias[threadIdx.x];
    __syncthreads();
    int lane = threadIdx.x & 31, wid = threadIdx.x >> 5;

    for (int node = blockIdx.x * 8 + wid; node < n; node += gridDim.x * 8) {
        int beg = __ldg(offs + node);
        int dg = __ldg(degs + node);
        int end = beg + dg;
        float ax0 = 0.f, ay0 = 0.f, ax1 = 0.f, ay1 = 0.f;
        int base = beg;
        // full 32-edge batches: unconditional, fully unrolled
        for (; base + 32 <= end; base += 32) {
            int sidx = __ldg(nbr + base + lane);
            #pragma unroll
            for (int j = 0; j < 32; j += 2) {
                int s0 = __shfl_sync(0xFFFFFFFFu, sidx, j);
                int s1 = __shfl_sync(0xFFFFFFFFu, sidx, j + 1);
                float2 v0 = __ldg(reinterpret_cast<const float2*>(xsrc + (size_t)s0 * 64) + lane);
                float2 v1 = __ldg(reinterpret_cast<const float2*>(xsrc + (size_t)s1 * 64) + lane);
                ax0 += v0.x; ay0 += v0.y;
                ax1 += v1.x; ay1 += v1.y;
            }
        }
        // masked tail batch: unconditional loads (idx 0 for invalid), predicated accumulate
        if (base < end) {
            int rem = end - base;           // 1..31, uniform across warp
            int sidx = (lane < rem) ? __ldg(nbr + base + lane) : 0;
            #pragma unroll
            for (int j = 0; j < 32; j += 2) {
                int s0 = __shfl_sync(0xFFFFFFFFu, sidx, j);
                int s1 = __shfl_sync(0xFFFFFFFFu, sidx, j + 1);
                float2 v0 = __ldg(reinterpret_cast<const float2*>(xsrc + (size_t)s0 * 64) + lane);
                float2 v1 = __ldg(reinterpret_cast<const float2*>(xsrc + (size_t)s1 * 64) + lane);
                if (j < rem)     { ax0 += v0.x; ay0 += v0.y; }
                if (j + 1 < rem) { ax1 += v1.x; ay1 += v1.y; }
            }
        }
        float accx = ax0 + ax1, accy = ay0 + ay1;
        float inv = 1.0f / fmaxf((float)dg, 1.0f);
        float2 x = *reinterpret_cast<const float2*>(xdst + (size_t)node * 64 + lane * 2);
        s_rows[wid][lane * 2]     = accx * inv;
        s_rows[wid][lane * 2 + 1] = accy * inv;
        s_rows[wid][64 + lane * 2]     = x.x;
        s_rows[wid][64 + lane * 2 + 1] = x.y;
        __syncwarp();
        float2 acc = make_float2(s_b[lane * 2], s_b[lane * 2 + 1]);
        #pragma unroll 8
        for (int k = 0; k < 64; k++) {
            float mk = s_rows[wid][k];
            float xk = s_rows[wid][64 + k];
            float2 wlv = *reinterpret_cast<const float2*>(s_wl + k * 64 + lane * 2);
            float2 wrv = *reinterpret_cast<const float2*>(s_wr + k * 64 + lane * 2);
            acc.x += mk * wlv.x + xk * wrv.x;
            acc.y += mk * wlv.y + xk * wrv.y;
        }
        if (RELU) { acc.x = fmaxf(acc.x, 0.f); acc.y = fmaxf(acc.y, 0.f); }
        *reinterpret_cast<float2*>(out + (size_t)node * 64 + lane * 2) = acc;
        __syncwarp();
    }
}

// ---------------- decoder precompute: out[n,128] = x[n,64] @ w[64,128] (+bias) --------
__global__ void dec_pre_kernel(const float* __restrict__ x, const float* __restrict__ w,
                               const float* __restrict__ bias, float* __restrict__ out, int n) {
    __shared__ __align__(16) float s_w[64 * 128];
    __shared__ float s_rows[8][64];
    for (int i = threadIdx.x; i < 64 * 128; i += blockDim.x) s_w[i] = w[i];
    __syncthreads();
    int lane = threadIdx.x & 31, wid = threadIdx.x >> 5;
    for (int node = blockIdx.x * 8 + wid; node < n; node += gridDim.x * 8) {
        float2 xv = *reinterpret_cast<const float2*>(x + (size_t)node * 64 + lane * 2);
        s_rows[wid][lane * 2] = xv.x;
        s_rows[wid][lane * 2 + 1] = xv.y;
        __syncwarp();
        float4 acc;
        if (bias) acc = *reinterpret_cast<const float4*>(bias + lane * 4);
        else      acc = make_float4(0.f, 0.f, 0.f, 0.f);
        #pragma unroll 8
        for (int k = 0; k < 64; k++) {
            float xk = s_rows[wid][k];
            float4 wv = *reinterpret_cast<const float4*>(s_w + k * 128 + lane * 4);
            acc.x += xk * wv.x; acc.y += xk * wv.y; acc.z += xk * wv.z; acc.w += xk * wv.w;
        }
        *reinterpret_cast<float4*>(out + (size_t)node * 128 + lane * 4) = acc;
        __syncwarp();
    }
}

// ---------------- decoder edge kernel (grid-stride, warp per edge) ----------------
__global__ void dec_edge_kernel(const float* __restrict__ Up, const float* __restrict__ Bp,
                                const int* __restrict__ ls, const int* __restrict__ ld,
                                const float* __restrict__ w2, const float* __restrict__ b2,
                                float* __restrict__ out, int m) {
    __shared__ float s_w2[128];
    if (threadIdx.x < 128) s_w2[threadIdx.x] = w2[threadIdx.x];
    __syncthreads();
    int lane = threadIdx.x & 31;
    int wid = threadIdx.x >> 5;
    float bb = __ldg(b2);
    for (int e = blockIdx.x * 8 + wid; e < m; e += gridDim.x * 8) {
        int s = __ldg(ls + e);
        int d = __ldg(ld + e);
        float4 a = *reinterpret_cast<const float4*>(Up + (size_t)s * 128 + lane * 4);
        float4 b = *reinterpret_cast<const float4*>(Bp + (size_t)d * 128 + lane * 4);
        float h0 = fmaxf(a.x + b.x, 0.f);
        float h1 = fmaxf(a.y + b.y, 0.f);
        float h2 = fmaxf(a.z + b.z, 0.f);
        float h3 = fmaxf(a.w + b.w, 0.f);
        float dot = h0 * s_w2[lane * 4] + h1 * s_w2[lane * 4 + 1]
                  + h2 * s_w2[lane * 4 + 2] + h3 * s_w2[lane * 4 + 3];
        #pragma unroll
        for (int off = 16; off > 0; off >>= 1)
            dot += __shfl_xor_sync(0xFFFFFFFFu, dot, off);
        if (lane == 0) out[e] = dot + bb;
    }
}

// ---------------- host launcher ----------------
extern "C" void kernel_launch(void* const* d_in, const int* in_sizes, int n_in,
                              void* d_out, int out_size) {
    const float* user_x    = (const float*)d_in[0];
    const float* book_x    = (const float*)d_in[1];
    const int*   edge_src  = (const int*)d_in[2];
    const int*   edge_dst  = (const int*)d_in[3];
    const int*   label_src = (const int*)d_in[4];
    const int*   label_dst = (const int*)d_in[5];
    const float* user_lin_w = (const float*)d_in[6];
    const float* user_lin_b = (const float*)d_in[7];
    const float* book_lin_w = (const float*)d_in[8];
    const float* book_lin_b = (const float*)d_in[9];
    const float* w1_ub_l = (const float*)d_in[10];
    const float* b1_ub   = (const float*)d_in[11];
    const float* w1_ub_r = (const float*)d_in[12];
    const float* w1_bu_l = (const float*)d_in[13];
    const float* b1_bu   = (const float*)d_in[14];
    const float* w1_bu_r = (const float*)d_in[15];
    const float* w2_ub_l = (const float*)d_in[16];
    const float* b2_ub   = (const float*)d_in[17];
    const float* w2_ub_r = (const float*)d_in[18];
    const float* w2_bu_l = (const float*)d_in[19];
    const float* b2_bu   = (const float*)d_in[20];
    const float* w2_bu_r = (const float*)d_in[21];
    const float* dec_w1  = (const float*)d_in[22];
    const float* dec_b1  = (const float*)d_in[23];
    const float* dec_w2  = (const float*)d_in[24];
    const float* dec_b2  = (const float*)d_in[25];

    int nu = in_sizes[0] / 3;
    int nb = in_sizes[1] / 384;
    int E  = in_sizes[2];
    int EL = in_sizes[4];
    float* out = (float*)d_out;

    float *u0, *b0, *u1, *b1, *u2, *b2, *up, *bp;
    int *degu, *degb, *offu, *offb, *curu, *curb, *nbu, *nub, *cnts;
    cudaGetSymbolAddress((void**)&u0, g_u0);
    cudaGetSymbolAddress((void**)&b0, g_b0);
    cudaGetSymbolAddress((void**)&u1, g_u1);
    cudaGetSymbolAddress((void**)&b1, g_b1);
    cudaGetSymbolAddress((void**)&u2, g_u2);
    cudaGetSymbolAddress((void**)&b2, g_b2);
    cudaGetSymbolAddress((void**)&up, g_up);
    cudaGetSymbolAddress((void**)&bp, g_bp);
    cudaGetSymbolAddress((void**)&degu, g_deg_u);
    cudaGetSymbolAddress((void**)&degb, g_deg_b);
    cudaGetSymbolAddress((void**)&offu, g_off_u);
    cudaGetSymbolAddress((void**)&offb, g_off_b);
    cudaGetSymbolAddress((void**)&curu, g_cur_u);
    cudaGetSymbolAddress((void**)&curb, g_cur_b);
    cudaGetSymbolAddress((void**)&nbu, g_nbr_b_of_u);
    cudaGetSymbolAddress((void**)&nub, g_nbr_u_of_b);
    cudaGetSymbolAddress((void**)&cnts, g_counters);

    static const int BOOK_SMEM = (384 * 64 + 32 * 96) * 4;
    cudaFuncSetAttribute(book_proj_kernel, cudaFuncAttributeMaxDynamicSharedMemorySize, BOOK_SMEM);

    // ---- CSR build ----
    zero_all_kernel<<<(nu + 255) / 256, 256>>>(degu, nu, degb, nb, cnts, 2);
    deg_kernel<<<(E / 2 + 255) / 256, 256>>>(edge_src, edge_dst, degu, degb, E);
    alloc_offsets_kernel<<<(nu + 1023) / 1024, 1024>>>(degu, offu, curu, cnts + 0, nu);
    alloc_offsets_kernel<<<(nb + 1023) / 1024, 1024>>>(degb, offb, curb, cnts + 1, nb);
    scatter_kernel<<<(E + 255) / 256, 256>>>(edge_src, edge_dst, curu, curb, nbu, nub, E);

    // ---- input projections ----
    {
        unsigned t = (unsigned)nu * 16u;
        user_proj_kernel<<<(t + 255) / 256, 256>>>(user_x, user_lin_w, user_lin_b, u0, nu);
    }
    book_proj_kernel<<<296, 256, BOOK_SMEM>>>(book_x, book_lin_w, book_lin_b, b0, nb);

    // ---- layer 1 (fused gather+transform, relu) ----
    sage_fused_kernel<true><<<888, 256>>>(u0, b0, offb, degb, nub, w1_ub_l, b1_ub, w1_ub_r, b1, nb);
    sage_fused_kernel<true><<<888, 256>>>(b0, u0, offu, degu, nbu, w1_bu_l, b1_bu, w1_bu_r, u1, nu);

    // ---- layer 2 (no relu) ----
    sage_fused_kernel<false><<<888, 256>>>(u1, b1, offb, degb, nub, w2_ub_l, b2_ub, w2_ub_r, b2, nb);
    sage_fused_kernel<false><<<888, 256>>>(b1, u1, offu, degu, nbu, w2_bu_l, b2_bu, w2_bu_r, u2, nu);

    // ---- decoder ----
    dec_pre_kernel<<<888, 256>>>(u2, dec_w1, dec_b1, up, nu);
    dec_pre_kernel<<<888, 256>>>(b2, dec_w1 + 64 * 128, nullptr, bp, nb);
    dec_edge_kernel<<<2048, 256>>>(up, bp, label_src, label_dst, dec_w2, dec_b2, out, EL);
}

// round 5
// speedup vs baseline: 1.5794x; 1.1030x over previous
#include <cuda_runtime.h>
#include <cstdint>
#include <cstddef>

#define NU_MAX 100000
#define NB_MAX 50000
#define E_MAX  2000000
#define C 64
#define H 128

// ---------------- device scratch (static, allocation-free) -----------
__device__ float g_u0[NU_MAX * C];
__device__ float g_b0[NB_MAX * C];
__device__ float g_u1[NU_MAX * C];
__device__ float g_b1[NB_MAX * C];
__device__ float g_u2[NU_MAX * C];
__device__ float g_b2[NB_MAX * C];
__device__ float g_up[NU_MAX * H];
__device__ float g_bp[NB_MAX * H];
// CSR structures
__device__ int g_deg_u[NU_MAX];
__device__ int g_deg_b[NB_MAX];
__device__ int g_off_u[NU_MAX];
__device__ int g_off_b[NB_MAX];
__device__ int g_cur_u[NU_MAX];
__device__ int g_cur_b[NB_MAX];
__device__ int g_nbr_b_of_u[E_MAX];
__device__ int g_nbr_u_of_b[E_MAX];
__device__ int g_counters[2];

// ---------------- utility ----------------
__global__ void zero_all_kernel(int* __restrict__ a, int na,
                                int* __restrict__ b, int nb_,
                                int* __restrict__ c, int nc) {
    int i = blockIdx.x * blockDim.x + threadIdx.x;
    if (i < na) a[i] = 0;
    if (i < nb_) b[i] = 0;
    if (i < nc) c[i] = 0;
}

__global__ void deg_kernel(const int* __restrict__ src, const int* __restrict__ dst,
                           int* __restrict__ degu, int* __restrict__ degb, int E) {
    int i = (blockIdx.x * blockDim.x + threadIdx.x) * 2;
    if (i + 1 < E) {
        int s0 = __ldg(src + i), s1 = __ldg(src + i + 1);
        int d0 = __ldg(dst + i), d1 = __ldg(dst + i + 1);
        atomicAdd(degu + s0, 1);
        atomicAdd(degu + s1, 1);
        atomicAdd(degb + d0, 1);
        atomicAdd(degb + d1, 1);
    } else if (i < E) {
        atomicAdd(degu + __ldg(src + i), 1);
        atomicAdd(degb + __ldg(dst + i), 1);
    }
}

// parallel segment allocation: block-local exclusive scan + atomic base grab.
__global__ void alloc_offsets_kernel(const int* __restrict__ deg, int* __restrict__ off,
                                     int* __restrict__ cur, int* __restrict__ counter, int n) {
    __shared__ int s_warp[32];
    __shared__ int s_base;
    int tid = threadIdx.x, lane = tid & 31, wid = tid >> 5;
    int i = blockIdx.x * 1024 + tid;
    int v = (i < n) ? deg[i] : 0;
    int x = v;
    #pragma unroll
    for (int o = 1; o < 32; o <<= 1) {
        int t = __shfl_up_sync(0xFFFFFFFFu, x, o);
        if (lane >= o) x += t;
    }
    if (lane == 31) s_warp[wid] = x;
    __syncthreads();
    if (wid == 0) {
        int w = s_warp[lane];
        #pragma unroll
        for (int o = 1; o < 32; o <<= 1) {
            int t = __shfl_up_sync(0xFFFFFFFFu, w, o);
            if (lane >= o) w += t;
        }
        s_warp[lane] = w;
    }
    __syncthreads();
    if (tid == 0) s_base = atomicAdd(counter, s_warp[31]);
    __syncthreads();
    int warpoff = (wid == 0) ? 0 : s_warp[wid - 1];
    int exc = s_base + warpoff + x - v;
    if (i < n) { off[i] = exc; cur[i] = exc; }
}

__global__ void scatter_kernel(const int* __restrict__ src, const int* __restrict__ dst,
                               int* __restrict__ curu, int* __restrict__ curb,
                               int* __restrict__ nbr_b_of_u, int* __restrict__ nbr_u_of_b,
                               int E) {
    int i = blockIdx.x * blockDim.x + threadIdx.x;
    if (i < E) {
        int s = src[i], d = dst[i];
        int pu = atomicAdd(curu + s, 1);
        nbr_b_of_u[pu] = d;
        int pb = atomicAdd(curb + d, 1);
        nbr_u_of_b[pb] = s;
    }
}

// ---------------- input projections ----------------
__global__ void user_proj_kernel(const float* __restrict__ x, const float* __restrict__ w,
                                 const float* __restrict__ b, float* __restrict__ out, int n) {
    unsigned i = blockIdx.x * blockDim.x + threadIdx.x;
    if (i >= (unsigned)n * 16u) return;
    unsigned node = i >> 4, j4 = (i & 15u) * 4;
    const float* xr = x + (size_t)node * 3;
    float x0 = __ldg(xr), x1 = __ldg(xr + 1), x2 = __ldg(xr + 2);
    float4 bb = __ldg(reinterpret_cast<const float4*>(b + j4));
    float4 w0 = __ldg(reinterpret_cast<const float4*>(w + j4));
    float4 w1 = __ldg(reinterpret_cast<const float4*>(w + 64 + j4));
    float4 w2 = __ldg(reinterpret_cast<const float4*>(w + 128 + j4));
    float4 r;
    r.x = bb.x + x0 * w0.x + x1 * w1.x + x2 * w2.x;
    r.y = bb.y + x0 * w0.y + x1 * w1.y + x2 * w2.y;
    r.z = bb.z + x0 * w0.z + x1 * w1.z + x2 * w2.z;
    r.w = bb.w + x0 * w0.w + x1 * w1.w + x2 * w2.w;
    *reinterpret_cast<float4*>(out + (size_t)node * 64 + j4) = r;
}

// book: [n,384] @ [384,64] + b, full weights in dynamic smem, grid-stride.
__global__ void book_proj_kernel(const float* __restrict__ x, const float* __restrict__ w,
                                 const float* __restrict__ bias, float* __restrict__ out, int n) {
    extern __shared__ float dsm[];
    float* s_w = dsm;                 // 384*64
    float* s_rc = dsm + 384 * 64;     // 32 rows x 96
    int tid = threadIdx.x, lane = tid & 31, wid = tid >> 5;
    const float4* wsrc = reinterpret_cast<const float4*>(w);
    float4* wdst = reinterpret_cast<float4*>(s_w);
    for (int i = tid; i < 384 * 64 / 4; i += 256) wdst[i] = __ldg(wsrc + i);
    float2 bb = make_float2(__ldg(bias + lane * 2), __ldg(bias + lane * 2 + 1));
    __syncthreads();

    for (int g = blockIdx.x * 32; g < n; g += gridDim.x * 32) {
        int node0 = g + wid * 4;
        float2 acc[4];
        #pragma unroll
        for (int r = 0; r < 4; r++) acc[r] = bb;
        for (int ch = 0; ch < 4; ch++) {
            #pragma unroll
            for (int r = 0; r < 4; r++) {
                int nd = node0 + r;
                if (nd < n) {
                    const float* xr = x + (size_t)nd * 384 + ch * 96;
                    float* dst = s_rc + (wid * 4 + r) * 96;
                    dst[lane] = __ldg(xr + lane);
                    dst[lane + 32] = __ldg(xr + lane + 32);
                    dst[lane + 64] = __ldg(xr + lane + 64);
                }
            }
            __syncwarp();
            const float* wch = s_w + ch * 96 * 64;
            #pragma unroll 8
            for (int k = 0; k < 96; k++) {
                float2 wv = *reinterpret_cast<const float2*>(wch + k * 64 + lane * 2);
                #pragma unroll
                for (int r = 0; r < 4; r++) {
                    float xv = s_rc[(wid * 4 + r) * 96 + k];
                    acc[r].x += xv * wv.x;
                    acc[r].y += xv * wv.y;
                }
            }
            __syncwarp();
        }
        #pragma unroll
        for (int r = 0; r < 4; r++) {
            int nd = node0 + r;
            if (nd < n)
                *reinterpret_cast<float2*>(out + (size_t)nd * 64 + lane * 2) = acc[r];
        }
    }
}

// ---------------- fused SAGE: half-warp per node, float4 lanes ----------------
// out[node] = (mean_{s in nbr(node)} xsrc[s]) @ wl + b + xdst[node] @ wr [, relu]
template <bool RELU>
__global__ void __launch_bounds__(256)
sage_fused_kernel(const float* __restrict__ xsrc, const float* __restrict__ xdst,
                  const int* __restrict__ offs, const int* __restrict__ degs,
                  const int* __restrict__ nbr,
                  const float* __restrict__ wl, const float* __restrict__ bias,
                  const float* __restrict__ wr,
                  float* __restrict__ out, int n) {
    __shared__ __align__(16) float s_wl[64 * 64];
    __shared__ __align__(16) float s_wr[64 * 64];
    __shared__ float s_b[64];
    __shared__ __align__(16) float s_rows[8][2][132];  // [warp][half][mean64|x64], padded
    for (int i = threadIdx.x; i < 64 * 64; i += blockDim.x) { s_wl[i] = wl[i]; s_wr[i] = wr[i]; }
    if (threadIdx.x < 64) s_b[threadIdx.x] = bias[threadIdx.x];
    __syncthreads();
    const unsigned FULL = 0xFFFFFFFFu;
    int lane = threadIdx.x & 31, wid = threadIdx.x >> 5;
    int lane16 = lane & 15, half = lane >> 4;

    for (int base = blockIdx.x * 16 + wid * 2; base < n; base += gridDim.x * 16) {
        int node = base + half;
        bool valid = node < n;
        int beg = 0, dg = 0;
        if (valid) { beg = __ldg(offs + node); dg = __ldg(degs + node); }
        int nb_h = (dg + 15) >> 4;
        int nb_o = __shfl_xor_sync(FULL, nb_h, 16);
        int nbatch = max(nb_h, nb_o);

        float4 a0 = make_float4(0.f, 0.f, 0.f, 0.f);
        float4 a1 = make_float4(0.f, 0.f, 0.f, 0.f);
        for (int b = 0; b < nbatch; b++) {
            int eoff = b * 16;
            int rem = dg - eoff;                       // may be <= 0 for this half
            int sidx = (lane16 < rem) ? __ldg(nbr + beg + eoff + lane16) : 0;
            #pragma unroll
            for (int j = 0; j < 16; j += 2) {
                int s0 = __shfl_sync(FULL, sidx, j, 16);
                int s1 = __shfl_sync(FULL, sidx, j + 1, 16);
                float4 v0 = __ldg(reinterpret_cast<const float4*>(xsrc + (size_t)s0 * 64) + lane16);
                float4 v1 = __ldg(reinterpret_cast<const float4*>(xsrc + (size_t)s1 * 64) + lane16);
                if (j < rem)     { a0.x += v0.x; a0.y += v0.y; a0.z += v0.z; a0.w += v0.w; }
                if (j + 1 < rem) { a1.x += v1.x; a1.y += v1.y; a1.z += v1.z; a1.w += v1.w; }
            }
        }
        float inv = 1.0f / fmaxf((float)dg, 1.0f);
        float4 mean4;
        mean4.x = (a0.x + a1.x) * inv;
        mean4.y = (a0.y + a1.y) * inv;
        mean4.z = (a0.z + a1.z) * inv;
        mean4.w = (a0.w + a1.w) * inv;
        float4 xv = make_float4(0.f, 0.f, 0.f, 0.f);
        if (valid)
            xv = *reinterpret_cast<const float4*>(xdst + (size_t)node * 64 + lane16 * 4);
        float* rw = &s_rows[wid][half][0];
        reinterpret_cast<float4*>(rw)[lane16] = mean4;
        reinterpret_cast<float4*>(rw + 64)[lane16] = xv;
        __syncwarp();
        float4 acc = *reinterpret_cast<const float4*>(s_b + lane16 * 4);
        #pragma unroll 8
        for (int k = 0; k < 64; k++) {
            float mk = rw[k];
            float xk = rw[64 + k];
            float4 wlv = *reinterpret_cast<const float4*>(s_wl + k * 64 + lane16 * 4);
            float4 wrv = *reinterpret_cast<const float4*>(s_wr + k * 64 + lane16 * 4);
            acc.x += mk * wlv.x + xk * wrv.x;
            acc.y += mk * wlv.y + xk * wrv.y;
            acc.z += mk * wlv.z + xk * wrv.z;
            acc.w += mk * wlv.w + xk * wrv.w;
        }
        if (RELU) {
            acc.x = fmaxf(acc.x, 0.f); acc.y = fmaxf(acc.y, 0.f);
            acc.z = fmaxf(acc.z, 0.f); acc.w = fmaxf(acc.w, 0.f);
        }
        if (valid)
            *reinterpret_cast<float4*>(out + (size_t)node * 64 + lane16 * 4) = acc;
        __syncwarp();
    }
}

// ---------------- decoder precompute: out[n,128] = x[n,64] @ w[64,128] (+bias) --------
__global__ void dec_pre_kernel(const float* __restrict__ x, const float* __restrict__ w,
                               const float* __restrict__ bias, float* __restrict__ out, int n) {
    __shared__ __align__(16) float s_w[64 * 128];
    __shared__ float s_rows[8][64];
    for (int i = threadIdx.x; i < 64 * 128; i += blockDim.x) s_w[i] = w[i];
    __syncthreads();
    int lane = threadIdx.x & 31, wid = threadIdx.x >> 5;
    for (int node = blockIdx.x * 8 + wid; node < n; node += gridDim.x * 8) {
        float2 xv = *reinterpret_cast<const float2*>(x + (size_t)node * 64 + lane * 2);
        s_rows[wid][lane * 2] = xv.x;
        s_rows[wid][lane * 2 + 1] = xv.y;
        __syncwarp();
        float4 acc;
        if (bias) acc = *reinterpret_cast<const float4*>(bias + lane * 4);
        else      acc = make_float4(0.f, 0.f, 0.f, 0.f);
        #pragma unroll 8
        for (int k = 0; k < 64; k++) {
            float xk = s_rows[wid][k];
            float4 wv = *reinterpret_cast<const float4*>(s_w + k * 128 + lane * 4);
            acc.x += xk * wv.x; acc.y += xk * wv.y; acc.z += xk * wv.z; acc.w += xk * wv.w;
        }
        *reinterpret_cast<float4*>(out + (size_t)node * 128 + lane * 4) = acc;
        __syncwarp();
    }
}

// ---------------- decoder edge kernel: 4 edges per warp iteration ----------------
__global__ void dec_edge_kernel(const float* __restrict__ Up, const float* __restrict__ Bp,
                                const int* __restrict__ ls, const int* __restrict__ ld,
                                const float* __restrict__ w2, const float* __restrict__ b2,
                                float* __restrict__ out, int m) {
    __shared__ float s_w2[128];
    if (threadIdx.x < 128) s_w2[threadIdx.x] = w2[threadIdx.x];
    __syncthreads();
    int lane = threadIdx.x & 31;
    int wid = threadIdx.x >> 5;
    float bb = __ldg(b2);
    float wq0 = s_w2[lane * 4], wq1 = s_w2[lane * 4 + 1];
    float wq2 = s_w2[lane * 4 + 2], wq3 = s_w2[lane * 4 + 3];
    int gwarp = blockIdx.x * 8 + wid;
    int stride = gridDim.x * 8;
    for (int e0 = gwarp * 4; e0 < m; e0 += stride * 4) {
        float dots[4];
        #pragma unroll
        for (int q = 0; q < 4; q++) {
            int e = e0 + q;
            float dot = 0.f;
            if (e < m) {
                int s = __ldg(ls + e);
                int d = __ldg(ld + e);
                float4 a = *reinterpret_cast<const float4*>(Up + (size_t)s * 128 + lane * 4);
                float4 b = *reinterpret_cast<const float4*>(Bp + (size_t)d * 128 + lane * 4);
                dot = fmaxf(a.x + b.x, 0.f) * wq0 + fmaxf(a.y + b.y, 0.f) * wq1
                    + fmaxf(a.z + b.z, 0.f) * wq2 + fmaxf(a.w + b.w, 0.f) * wq3;
            }
            dots[q] = dot;
        }
        #pragma unroll
        for (int off = 16; off > 0; off >>= 1) {
            dots[0] += __shfl_xor_sync(0xFFFFFFFFu, dots[0], off);
            dots[1] += __shfl_xor_sync(0xFFFFFFFFu, dots[1], off);
            dots[2] += __shfl_xor_sync(0xFFFFFFFFu, dots[2], off);
            dots[3] += __shfl_xor_sync(0xFFFFFFFFu, dots[3], off);
        }
        if (lane == 0) {
            #pragma unroll
            for (int q = 0; q < 4; q++)
                if (e0 + q < m) out[e0 + q] = dots[q] + bb;
        }
    }
}

// ---------------- host launcher ----------------
extern "C" void kernel_launch(void* const* d_in, const int* in_sizes, int n_in,
                              void* d_out, int out_size) {
    const float* user_x    = (const float*)d_in[0];
    const float* book_x    = (const float*)d_in[1];
    const int*   edge_src  = (const int*)d_in[2];
    const int*   edge_dst  = (const int*)d_in[3];
    const int*   label_src = (const int*)d_in[4];
    const int*   label_dst = (const int*)d_in[5];
    const float* user_lin_w = (const float*)d_in[6];
    const float* user_lin_b = (const float*)d_in[7];
    const float* book_lin_w = (const float*)d_in[8];
    const float* book_lin_b = (const float*)d_in[9];
    const float* w1_ub_l = (const float*)d_in[10];
    const float* b1_ub   = (const float*)d_in[11];
    const float* w1_ub_r = (const float*)d_in[12];
    const float* w1_bu_l = (const float*)d_in[13];
    const float* b1_bu   = (const float*)d_in[14];
    const float* w1_bu_r = (const float*)d_in[15];
    const float* w2_ub_l = (const float*)d_in[16];
    const float* b2_ub   = (const float*)d_in[17];
    const float* w2_ub_r = (const float*)d_in[18];
    const float* w2_bu_l = (const float*)d_in[19];
    const float* b2_bu   = (const float*)d_in[20];
    const float* w2_bu_r = (const float*)d_in[21];
    const float* dec_w1  = (const float*)d_in[22];
    const float* dec_b1  = (const float*)d_in[23];
    const float* dec_w2  = (const float*)d_in[24];
    const float* dec_b2  = (const float*)d_in[25];

    int nu = in_sizes[0] / 3;
    int nb = in_sizes[1] / 384;
    int E  = in_sizes[2];
    int EL = in_sizes[4];
    float* out = (float*)d_out;

    float *u0, *b0, *u1, *b1, *u2, *b2, *up, *bp;
    int *degu, *degb, *offu, *offb, *curu, *curb, *nbu, *nub, *cnts;
    cudaGetSymbolAddress((void**)&u0, g_u0);
    cudaGetSymbolAddress((void**)&b0, g_b0);
    cudaGetSymbolAddress((void**)&u1, g_u1);
    cudaGetSymbolAddress((void**)&b1, g_b1);
    cudaGetSymbolAddress((void**)&u2, g_u2);
    cudaGetSymbolAddress((void**)&b2, g_b2);
    cudaGetSymbolAddress((void**)&up, g_up);
    cudaGetSymbolAddress((void**)&bp, g_bp);
    cudaGetSymbolAddress((void**)&degu, g_deg_u);
    cudaGetSymbolAddress((void**)&degb, g_deg_b);
    cudaGetSymbolAddress((void**)&offu, g_off_u);
    cudaGetSymbolAddress((void**)&offb, g_off_b);
    cudaGetSymbolAddress((void**)&curu, g_cur_u);
    cudaGetSymbolAddress((void**)&curb, g_cur_b);
    cudaGetSymbolAddress((void**)&nbu, g_nbr_b_of_u);
    cudaGetSymbolAddress((void**)&nub, g_nbr_u_of_b);
    cudaGetSymbolAddress((void**)&cnts, g_counters);

    static const int BOOK_SMEM = (384 * 64 + 32 * 96) * 4;
    cudaFuncSetAttribute(book_proj_kernel, cudaFuncAttributeMaxDynamicSharedMemorySize, BOOK_SMEM);

    // ---- CSR build ----
    zero_all_kernel<<<(nu + 255) / 256, 256>>>(degu, nu, degb, nb, cnts, 2);
    deg_kernel<<<(E / 2 + 255) / 256, 256>>>(edge_src, edge_dst, degu, degb, E);
    alloc_offsets_kernel<<<(nu + 1023) / 1024, 1024>>>(degu, offu, curu, cnts + 0, nu);
    alloc_offsets_kernel<<<(nb + 1023) / 1024, 1024>>>(degb, offb, curb, cnts + 1, nb);
    scatter_kernel<<<(E + 255) / 256, 256>>>(edge_src, edge_dst, curu, curb, nbu, nub, E);

    // ---- input projections ----
    {
        unsigned t = (unsigned)nu * 16u;
        user_proj_kernel<<<(t + 255) / 256, 256>>>(user_x, user_lin_w, user_lin_b, u0, nu);
    }
    book_proj_kernel<<<296, 256, BOOK_SMEM>>>(book_x, book_lin_w, book_lin_b, b0, nb);

    // ---- layer 1 (fused gather+transform, relu) ----
    sage_fused_kernel<true><<<888, 256>>>(u0, b0, offb, degb, nub, w1_ub_l, b1_ub, w1_ub_r, b1, nb);
    sage_fused_kernel<true><<<888, 256>>>(b0, u0, offu, degu, nbu, w1_bu_l, b1_bu, w1_bu_r, u1, nu);

    // ---- layer 2 (no relu) ----
    sage_fused_kernel<false><<<888, 256>>>(u1, b1, offb, degb, nub, w2_ub_l, b2_ub, w2_ub_r, b2, nb);
    sage_fused_kernel<false><<<888, 256>>>(b1, u1, offu, degu, nbu, w2_bu_l, b2_bu, w2_bu_r, u2, nu);

    // ---- decoder ----
    dec_pre_kernel<<<888, 256>>>(u2, dec_w1, dec_b1, up, nu);
    dec_pre_kernel<<<888, 256>>>(b2, dec_w1 + 64 * 128, nullptr, bp, nb);
    dec_edge_kernel<<<1024, 256>>>(up, bp, label_src, label_dst, dec_w2, dec_b2, out, EL);
}

// round 6
// speedup vs baseline: 1.6191x; 1.0252x over previous
#include <cuda_runtime.h>
#include <cuda_fp16.h>
#include <cstdint>
#include <cstddef>

#define NU_MAX 100000
#define NB_MAX 50000
#define E_MAX  2000000
#define C 64
#define H 128

// ---------------- device scratch (static, allocation-free) -----------
__device__ float g_u0[NU_MAX * C];
__device__ float g_b0[NB_MAX * C];
__device__ float g_u1[NU_MAX * C];
__device__ float g_b1[NB_MAX * C];
__device__ float g_u2[NU_MAX * C];
__device__ float g_b2[NB_MAX * C];
__device__ __half g_u0h[NU_MAX * C];
__device__ __half g_b0h[NB_MAX * C];
__device__ __half g_u1h[NU_MAX * C];
__device__ __half g_b1h[NB_MAX * C];
__device__ __half g_uph[NU_MAX * H];
__device__ __half g_bph[NB_MAX * H];
// CSR structures
__device__ int g_deg_u[NU_MAX];
__device__ int g_deg_b[NB_MAX];
__device__ int g_off_u[NU_MAX];
__device__ int g_off_b[NB_MAX];
__device__ int g_cur_u[NU_MAX];
__device__ int g_cur_b[NB_MAX];
__device__ int g_nbr_b_of_u[E_MAX];
__device__ int g_nbr_u_of_b[E_MAX];
__device__ int g_counters[2];

static __device__ __forceinline__ uint2 pack_half4(float a, float b, float c, float d) {
    __half2 h01 = __floats2half2_rn(a, b);
    __half2 h23 = __floats2half2_rn(c, d);
    uint2 r;
    r.x = *reinterpret_cast<unsigned*>(&h01);
    r.y = *reinterpret_cast<unsigned*>(&h23);
    return r;
}

// ---------------- utility ----------------
__global__ void zero_all_kernel(int* __restrict__ a, int na,
                                int* __restrict__ b, int nb_,
                                int* __restrict__ c, int nc) {
    int i = blockIdx.x * blockDim.x + threadIdx.x;
    if (i < na) a[i] = 0;
    if (i < nb_) b[i] = 0;
    if (i < nc) c[i] = 0;
}

__global__ void deg_kernel(const int* __restrict__ src, const int* __restrict__ dst,
                           int* __restrict__ degu, int* __restrict__ degb, int E) {
    int i = (blockIdx.x * blockDim.x + threadIdx.x) * 2;
    if (i + 1 < E) {
        int s0 = __ldg(src + i), s1 = __ldg(src + i + 1);
        int d0 = __ldg(dst + i), d1 = __ldg(dst + i + 1);
        atomicAdd(degu + s0, 1);
        atomicAdd(degu + s1, 1);
        atomicAdd(degb + d0, 1);
        atomicAdd(degb + d1, 1);
    } else if (i < E) {
        atomicAdd(degu + __ldg(src + i), 1);
        atomicAdd(degb + __ldg(dst + i), 1);
    }
}

// fused parallel segment allocation for both sides.
__global__ void alloc_offsets2_kernel(const int* __restrict__ degu, int* __restrict__ offu,
                                      int* __restrict__ curu,
                                      const int* __restrict__ degb, int* __restrict__ offb,
                                      int* __restrict__ curb,
                                      int* __restrict__ counters, int nu, int nb, int gu) {
    bool isU = (int)blockIdx.x < gu;
    const int* deg = isU ? degu : degb;
    int* off = isU ? offu : offb;
    int* cur = isU ? curu : curb;
    int* counter = counters + (isU ? 0 : 1);
    int n = isU ? nu : nb;
    int bid = isU ? blockIdx.x : blockIdx.x - gu;

    __shared__ int s_warp[32];
    __shared__ int s_base;
    int tid = threadIdx.x, lane = tid & 31, wid = tid >> 5;
    int i = bid * 1024 + tid;
    int v = (i < n) ? deg[i] : 0;
    int x = v;
    #pragma unroll
    for (int o = 1; o < 32; o <<= 1) {
        int t = __shfl_up_sync(0xFFFFFFFFu, x, o);
        if (lane >= o) x += t;
    }
    if (lane == 31) s_warp[wid] = x;
    __syncthreads();
    if (wid == 0) {
        int w = s_warp[lane];
        #pragma unroll
        for (int o = 1; o < 32; o <<= 1) {
            int t = __shfl_up_sync(0xFFFFFFFFu, w, o);
            if (lane >= o) w += t;
        }
        s_warp[lane] = w;
    }
    __syncthreads();
    if (tid == 0) s_base = atomicAdd(counter, s_warp[31]);
    __syncthreads();
    int warpoff = (wid == 0) ? 0 : s_warp[wid - 1];
    int exc = s_base + warpoff + x - v;
    if (i < n) { off[i] = exc; cur[i] = exc; }
}

__global__ void scatter_kernel(const int* __restrict__ src, const int* __restrict__ dst,
                               int* __restrict__ curu, int* __restrict__ curb,
                               int* __restrict__ nbr_b_of_u, int* __restrict__ nbr_u_of_b,
                               int E) {
    int i = blockIdx.x * blockDim.x + threadIdx.x;
    if (i < E) {
        int s = src[i], d = dst[i];
        int pu = atomicAdd(curu + s, 1);
        nbr_b_of_u[pu] = d;
        int pb = atomicAdd(curb + d, 1);
        nbr_u_of_b[pb] = s;
    }
}

// ---------------- input projections (emit fp32 + fp16) ----------------
__global__ void user_proj_kernel(const float* __restrict__ x, const float* __restrict__ w,
                                 const float* __restrict__ b, float* __restrict__ out,
                                 __half* __restrict__ outh, int n) {
    unsigned i = blockIdx.x * blockDim.x + threadIdx.x;
    if (i >= (unsigned)n * 16u) return;
    unsigned node = i >> 4, j4 = (i & 15u) * 4;
    const float* xr = x + (size_t)node * 3;
    float x0 = __ldg(xr), x1 = __ldg(xr + 1), x2 = __ldg(xr + 2);
    float4 bb = __ldg(reinterpret_cast<const float4*>(b + j4));
    float4 w0 = __ldg(reinterpret_cast<const float4*>(w + j4));
    float4 w1 = __ldg(reinterpret_cast<const float4*>(w + 64 + j4));
    float4 w2 = __ldg(reinterpret_cast<const float4*>(w + 128 + j4));
    float4 r;
    r.x = bb.x + x0 * w0.x + x1 * w1.x + x2 * w2.x;
    r.y = bb.y + x0 * w0.y + x1 * w1.y + x2 * w2.y;
    r.z = bb.z + x0 * w0.z + x1 * w1.z + x2 * w2.z;
    r.w = bb.w + x0 * w0.w + x1 * w1.w + x2 * w2.w;
    *reinterpret_cast<float4*>(out + (size_t)node * 64 + j4) = r;
    *reinterpret_cast<uint2*>(outh + (size_t)node * 64 + j4) = pack_half4(r.x, r.y, r.z, r.w);
}

// book: [n,384] @ [384,64] + b, full weights in dynamic smem, grid-stride.
__global__ void book_proj_kernel(const float* __restrict__ x, const float* __restrict__ w,
                                 const float* __restrict__ bias, float* __restrict__ out,
                                 __half* __restrict__ outh, int n) {
    extern __shared__ float dsm[];
    float* s_w = dsm;                 // 384*64
    float* s_rc = dsm + 384 * 64;     // 32 rows x 96
    int tid = threadIdx.x, lane = tid & 31, wid = tid >> 5;
    const float4* wsrc = reinterpret_cast<const float4*>(w);
    float4* wdst = reinterpret_cast<float4*>(s_w);
    for (int i = tid; i < 384 * 64 / 4; i += 256) wdst[i] = __ldg(wsrc + i);
    float2 bb = make_float2(__ldg(bias + lane * 2), __ldg(bias + lane * 2 + 1));
    __syncthreads();

    for (int g = blockIdx.x * 32; g < n; g += gridDim.x * 32) {
        int node0 = g + wid * 4;
        float2 acc[4];
        #pragma unroll
        for (int r = 0; r < 4; r++) acc[r] = bb;
        for (int ch = 0; ch < 4; ch++) {
            #pragma unroll
            for (int r = 0; r < 4; r++) {
                int nd = node0 + r;
                if (nd < n) {
                    const float* xr = x + (size_t)nd * 384 + ch * 96;
                    float* dst = s_rc + (wid * 4 + r) * 96;
                    dst[lane] = __ldg(xr + lane);
                    dst[lane + 32] = __ldg(xr + lane + 32);
                    dst[lane + 64] = __ldg(xr + lane + 64);
                }
            }
            __syncwarp();
            const float* wch = s_w + ch * 96 * 64;
            #pragma unroll 8
            for (int k = 0; k < 96; k++) {
                float2 wv = *reinterpret_cast<const float2*>(wch + k * 64 + lane * 2);
                #pragma unroll
                for (int r = 0; r < 4; r++) {
                    float xv = s_rc[(wid * 4 + r) * 96 + k];
                    acc[r].x += xv * wv.x;
                    acc[r].y += xv * wv.y;
                }
            }
            __syncwarp();
        }
        #pragma unroll
        for (int r = 0; r < 4; r++) {
            int nd = node0 + r;
            if (nd < n) {
                *reinterpret_cast<float2*>(out + (size_t)nd * 64 + lane * 2) = acc[r];
                __half2 h = __floats2half2_rn(acc[r].x, acc[r].y);
                *reinterpret_cast<unsigned*>(outh + (size_t)nd * 64 + lane * 2) =
                    *reinterpret_cast<unsigned*>(&h);
            }
        }
    }
}

// ---------------- fused SAGE: half-warp per node, fp16 gather, fp32 math --------------
// out[node] = (mean_{s in nbr(node)} xsrc[s]) @ wl + b + xdst[node] @ wr [, relu]
template <bool RELU, bool EMIT_H>
__global__ void __launch_bounds__(256)
sage_fused_kernel(const __half* __restrict__ xsrc, const float* __restrict__ xdst,
                  const int* __restrict__ offs, const int* __restrict__ degs,
                  const int* __restrict__ nbr,
                  const float* __restrict__ wl, const float* __restrict__ bias,
                  const float* __restrict__ wr,
                  float* __restrict__ out, __half* __restrict__ outh, int n) {
    __shared__ __align__(16) float s_wl[64 * 64];
    __shared__ __align__(16) float s_wr[64 * 64];
    __shared__ float s_b[64];
    __shared__ __align__(16) float s_rows[8][2][132];
    for (int i = threadIdx.x; i < 64 * 64; i += blockDim.x) { s_wl[i] = wl[i]; s_wr[i] = wr[i]; }
    if (threadIdx.x < 64) s_b[threadIdx.x] = bias[threadIdx.x];
    __syncthreads();
    const unsigned FULL = 0xFFFFFFFFu;
    int lane = threadIdx.x & 31, wid = threadIdx.x >> 5;
    int lane16 = lane & 15, half = lane >> 4;

    for (int base = blockIdx.x * 16 + wid * 2; base < n; base += gridDim.x * 16) {
        int node = base + half;
        bool valid = node < n;
        int beg = 0, dg = 0;
        if (valid) { beg = __ldg(offs + node); dg = __ldg(degs + node); }
        int nb_h = (dg + 15) >> 4;
        int nb_o = __shfl_xor_sync(FULL, nb_h, 16);
        int nbatch = max(nb_h, nb_o);

        float4 a0 = make_float4(0.f, 0.f, 0.f, 0.f);
        float4 a1 = make_float4(0.f, 0.f, 0.f, 0.f);
        float4 a2 = make_float4(0.f, 0.f, 0.f, 0.f);
        float4 a3 = make_float4(0.f, 0.f, 0.f, 0.f);
        for (int b = 0; b < nbatch; b++) {
            int eoff = b * 16;
            int rem = dg - eoff;
            int sidx = (lane16 < rem) ? __ldg(nbr + beg + eoff + lane16) : 0;
            #pragma unroll
            for (int j = 0; j < 16; j += 4) {
                int s0 = __shfl_sync(FULL, sidx, j, 16);
                int s1 = __shfl_sync(FULL, sidx, j + 1, 16);
                int s2 = __shfl_sync(FULL, sidx, j + 2, 16);
                int s3 = __shfl_sync(FULL, sidx, j + 3, 16);
                uint2 r0 = __ldg(reinterpret_cast<const uint2*>(xsrc + (size_t)s0 * 64) + lane16);
                uint2 r1 = __ldg(reinterpret_cast<const uint2*>(xsrc + (size_t)s1 * 64) + lane16);
                uint2 r2 = __ldg(reinterpret_cast<const uint2*>(xsrc + (size_t)s2 * 64) + lane16);
                uint2 r3 = __ldg(reinterpret_cast<const uint2*>(xsrc + (size_t)s3 * 64) + lane16);
                if (j < rem) {
                    float2 lo = __half22float2(*reinterpret_cast<__half2*>(&r0.x));
                    float2 hi = __half22float2(*reinterpret_cast<__half2*>(&r0.y));
                    a0.x += lo.x; a0.y += lo.y; a0.z += hi.x; a0.w += hi.y;
                }
                if (j + 1 < rem) {
                    float2 lo = __half22float2(*reinterpret_cast<__half2*>(&r1.x));
                    float2 hi = __half22float2(*reinterpret_cast<__half2*>(&r1.y));
                    a1.x += lo.x; a1.y += lo.y; a1.z += hi.x; a1.w += hi.y;
                }
                if (j + 2 < rem) {
                    float2 lo = __half22float2(*reinterpret_cast<__half2*>(&r2.x));
                    float2 hi = __half22float2(*reinterpret_cast<__half2*>(&r2.y));
                    a2.x += lo.x; a2.y += lo.y; a2.z += hi.x; a2.w += hi.y;
                }
                if (j + 3 < rem) {
                    float2 lo = __half22float2(*reinterpret_cast<__half2*>(&r3.x));
                    float2 hi = __half22float2(*reinterpret_cast<__half2*>(&r3.y));
                    a3.x += lo.x; a3.y += lo.y; a3.z += hi.x; a3.w += hi.y;
                }
            }
        }
        float inv = 1.0f / fmaxf((float)dg, 1.0f);
        float4 mean4;
        mean4.x = (a0.x + a1.x + a2.x + a3.x) * inv;
        mean4.y = (a0.y + a1.y + a2.y + a3.y) * inv;
        mean4.z = (a0.z + a1.z + a2.z + a3.z) * inv;
        mean4.w = (a0.w + a1.w + a2.w + a3.w) * inv;
        float4 xv = make_float4(0.f, 0.f, 0.f, 0.f);
        if (valid)
            xv = *reinterpret_cast<const float4*>(xdst + (size_t)node * 64 + lane16 * 4);
        float* rw = &s_rows[wid][half][0];
        reinterpret_cast<float4*>(rw)[lane16] = mean4;
        reinterpret_cast<float4*>(rw + 64)[lane16] = xv;
        __syncwarp();
        float4 acc = *reinterpret_cast<const float4*>(s_b + lane16 * 4);
        #pragma unroll 8
        for (int k = 0; k < 64; k++) {
            float mk = rw[k];
            float xk = rw[64 + k];
            float4 wlv = *reinterpret_cast<const float4*>(s_wl + k * 64 + lane16 * 4);
            float4 wrv = *reinterpret_cast<const float4*>(s_wr + k * 64 + lane16 * 4);
            acc.x += mk * wlv.x + xk * wrv.x;
            acc.y += mk * wlv.y + xk * wrv.y;
            acc.z += mk * wlv.z + xk * wrv.z;
            acc.w += mk * wlv.w + xk * wrv.w;
        }
        if (RELU) {
            acc.x = fmaxf(acc.x, 0.f); acc.y = fmaxf(acc.y, 0.f);
            acc.z = fmaxf(acc.z, 0.f); acc.w = fmaxf(acc.w, 0.f);
        }
        if (valid) {
            *reinterpret_cast<float4*>(out + (size_t)node * 64 + lane16 * 4) = acc;
            if (EMIT_H)
                *reinterpret_cast<uint2*>(outh + (size_t)node * 64 + lane16 * 4) =
                    pack_half4(acc.x, acc.y, acc.z, acc.w);
        }
        __syncwarp();
    }
}

// ---------------- decoder precompute: out[n,128](fp16) = x[n,64] @ w[64,128] (+bias) --
__global__ void dec_pre_kernel(const float* __restrict__ x, const float* __restrict__ w,
                               const float* __restrict__ bias, __half* __restrict__ out, int n) {
    __shared__ __align__(16) float s_w[64 * 128];
    __shared__ float s_rows[8][64];
    for (int i = threadIdx.x; i < 64 * 128; i += blockDim.x) s_w[i] = w[i];
    __syncthreads();
    int lane = threadIdx.x & 31, wid = threadIdx.x >> 5;
    for (int node = blockIdx.x * 8 + wid; node < n; node += gridDim.x * 8) {
        float2 xv = *reinterpret_cast<const float2*>(x + (size_t)node * 64 + lane * 2);
        s_rows[wid][lane * 2] = xv.x;
        s_rows[wid][lane * 2 + 1] = xv.y;
        __syncwarp();
        float4 acc;
        if (bias) acc = *reinterpret_cast<const float4*>(bias + lane * 4);
        else      acc = make_float4(0.f, 0.f, 0.f, 0.f);
        #pragma unroll 8
        for (int k = 0; k < 64; k++) {
            float xk = s_rows[wid][k];
            float4 wv = *reinterpret_cast<const float4*>(s_w + k * 128 + lane * 4);
            acc.x += xk * wv.x; acc.y += xk * wv.y; acc.z += xk * wv.z; acc.w += xk * wv.w;
        }
        *reinterpret_cast<uint2*>(out + (size_t)node * 128 + lane * 4) =
            pack_half4(acc.x, acc.y, acc.z, acc.w);
        __syncwarp();
    }
}

// ---------------- decoder edge kernel: fp16 tables, 4 edges per warp iteration -------
__global__ void dec_edge_kernel(const __half* __restrict__ Up, const __half* __restrict__ Bp,
                                const int* __restrict__ ls, const int* __restrict__ ld,
                                const float* __restrict__ w2, const float* __restrict__ b2,
                                float* __restrict__ out, int m) {
    __shared__ float s_w2[128];
    if (threadIdx.x < 128) s_w2[threadIdx.x] = w2[threadIdx.x];
    __syncthreads();
    int lane = threadIdx.x & 31;
    int wid = threadIdx.x >> 5;
    float bb = __ldg(b2);
    float wq0 = s_w2[lane * 4], wq1 = s_w2[lane * 4 + 1];
    float wq2 = s_w2[lane * 4 + 2], wq3 = s_w2[lane * 4 + 3];
    int gwarp = blockIdx.x * 8 + wid;
    int stride = gridDim.x * 8;
    for (int e0 = gwarp * 4; e0 < m; e0 += stride * 4) {
        float dots[4];
        #pragma unroll
        for (int q = 0; q < 4; q++) {
            int e = e0 + q;
            float dot = 0.f;
            if (e < m) {
                int s = __ldg(ls + e);
                int d = __ldg(ld + e);
                uint2 ra = __ldg(reinterpret_cast<const uint2*>(Up + (size_t)s * 128) + lane);
                uint2 rb = __ldg(reinterpret_cast<const uint2*>(Bp + (size_t)d * 128) + lane);
                float2 a01 = __half22float2(*reinterpret_cast<__half2*>(&ra.x));
                float2 a23 = __half22float2(*reinterpret_cast<__half2*>(&ra.y));
                float2 b01 = __half22float2(*reinterpret_cast<__half2*>(&rb.x));
                float2 b23 = __half22float2(*reinterpret_cast<__half2*>(&rb.y));
                dot = fmaxf(a01.x + b01.x, 0.f) * wq0 + fmaxf(a01.y + b01.y, 0.f) * wq1
                    + fmaxf(a23.x + b23.x, 0.f) * wq2 + fmaxf(a23.y + b23.y, 0.f) * wq3;
            }
            dots[q] = dot;
        }
        #pragma unroll
        for (int off = 16; off > 0; off >>= 1) {
            dots[0] += __shfl_xor_sync(0xFFFFFFFFu, dots[0], off);
            dots[1] += __shfl_xor_sync(0xFFFFFFFFu, dots[1], off);
            dots[2] += __shfl_xor_sync(0xFFFFFFFFu, dots[2], off);
            dots[3] += __shfl_xor_sync(0xFFFFFFFFu, dots[3], off);
        }
        if (lane == 0) {
            #pragma unroll
            for (int q = 0; q < 4; q++)
                if (e0 + q < m) out[e0 + q] = dots[q] + bb;
        }
    }
}

// ---------------- host launcher ----------------
extern "C" void kernel_launch(void* const* d_in, const int* in_sizes, int n_in,
                              void* d_out, int out_size) {
    const float* user_x    = (const float*)d_in[0];
    const float* book_x    = (const float*)d_in[1];
    const int*   edge_src  = (const int*)d_in[2];
    const int*   edge_dst  = (const int*)d_in[3];
    const int*   label_src = (const int*)d_in[4];
    const int*   label_dst = (const int*)d_in[5];
    const float* user_lin_w = (const float*)d_in[6];
    const float* user_lin_b = (const float*)d_in[7];
    const float* book_lin_w = (const float*)d_in[8];
    const float* book_lin_b = (const float*)d_in[9];
    const float* w1_ub_l = (const float*)d_in[10];
    const float* b1_ub   = (const float*)d_in[11];
    const float* w1_ub_r = (const float*)d_in[12];
    const float* w1_bu_l = (const float*)d_in[13];
    const float* b1_bu   = (const float*)d_in[14];
    const float* w1_bu_r = (const float*)d_in[15];
    const float* w2_ub_l = (const float*)d_in[16];
    const float* b2_ub   = (const float*)d_in[17];
    const float* w2_ub_r = (const float*)d_in[18];
    const float* w2_bu_l = (const float*)d_in[19];
    const float* b2_bu   = (const float*)d_in[20];
    const float* w2_bu_r = (const float*)d_in[21];
    const float* dec_w1  = (const float*)d_in[22];
    const float* dec_b1  = (const float*)d_in[23];
    const float* dec_w2  = (const float*)d_in[24];
    const float* dec_b2  = (const float*)d_in[25];

    int nu = in_sizes[0] / 3;
    int nb = in_sizes[1] / 384;
    int E  = in_sizes[2];
    int EL = in_sizes[4];
    float* out = (float*)d_out;

    float *u0, *b0, *u1, *b1, *u2, *b2;
    __half *u0h, *b0h, *u1h, *b1h, *uph, *bph;
    int *degu, *degb, *offu, *offb, *curu, *curb, *nbu, *nub, *cnts;
    cudaGetSymbolAddress((void**)&u0, g_u0);
    cudaGetSymbolAddress((void**)&b0, g_b0);
    cudaGetSymbolAddress((void**)&u1, g_u1);
    cudaGetSymbolAddress((void**)&b1, g_b1);
    cudaGetSymbolAddress((void**)&u2, g_u2);
    cudaGetSymbolAddress((void**)&b2, g_b2);
    cudaGetSymbolAddress((void**)&u0h, g_u0h);
    cudaGetSymbolAddress((void**)&b0h, g_b0h);
    cudaGetSymbolAddress((void**)&u1h, g_u1h);
    cudaGetSymbolAddress((void**)&b1h, g_b1h);
    cudaGetSymbolAddress((void**)&uph, g_uph);
    cudaGetSymbolAddress((void**)&bph, g_bph);
    cudaGetSymbolAddress((void**)&degu, g_deg_u);
    cudaGetSymbolAddress((void**)&degb, g_deg_b);
    cudaGetSymbolAddress((void**)&offu, g_off_u);
    cudaGetSymbolAddress((void**)&offb, g_off_b);
    cudaGetSymbolAddress((void**)&curu, g_cur_u);
    cudaGetSymbolAddress((void**)&curb, g_cur_b);
    cudaGetSymbolAddress((void**)&nbu, g_nbr_b_of_u);
    cudaGetSymbolAddress((void**)&nub, g_nbr_u_of_b);
    cudaGetSymbolAddress((void**)&cnts, g_counters);

    static const int BOOK_SMEM = (384 * 64 + 32 * 96) * 4;
    cudaFuncSetAttribute(book_proj_kernel, cudaFuncAttributeMaxDynamicSharedMemorySize, BOOK_SMEM);

    // ---- CSR build ----
    zero_all_kernel<<<(nu + 255) / 256, 256>>>(degu, nu, degb, nb, cnts, 2);
    deg_kernel<<<(E / 2 + 255) / 256, 256>>>(edge_src, edge_dst, degu, degb, E);
    int gu = (nu + 1023) / 1024, gb = (nb + 1023) / 1024;
    alloc_offsets2_kernel<<<gu + gb, 1024>>>(degu, offu, curu, degb, offb, curb, cnts, nu, nb, gu);
    scatter_kernel<<<(E + 255) / 256, 256>>>(edge_src, edge_dst, curu, curb, nbu, nub, E);

    // ---- input projections ----
    {
        unsigned t = (unsigned)nu * 16u;
        user_proj_kernel<<<(t + 255) / 256, 256>>>(user_x, user_lin_w, user_lin_b, u0, u0h, nu);
    }
    book_proj_kernel<<<296, 256, BOOK_SMEM>>>(book_x, book_lin_w, book_lin_b, b0, b0h, nb);

    // ---- layer 1 (fused gather+transform, relu, emit fp16) ----
    sage_fused_kernel<true, true><<<888, 256>>>(u0h, b0, offb, degb, nub, w1_ub_l, b1_ub, w1_ub_r, b1, b1h, nb);
    sage_fused_kernel<true, true><<<888, 256>>>(b0h, u0, offu, degu, nbu, w1_bu_l, b1_bu, w1_bu_r, u1, u1h, nu);

    // ---- layer 2 (no relu, fp32 only) ----
    sage_fused_kernel<false, false><<<888, 256>>>(u1h, b1, offb, degb, nub, w2_ub_l, b2_ub, w2_ub_r, b2, nullptr, nb);
    sage_fused_kernel<false, false><<<888, 256>>>(b1h, u1, offu, degu, nbu, w2_bu_l, b2_bu, w2_bu_r, u2, nullptr, nu);

    // ---- decoder ----
    dec_pre_kernel<<<888, 256>>>(u2, dec_w1, dec_b1, uph, nu);
    dec_pre_kernel<<<888, 256>>>(b2, dec_w1 + 64 * 128, nullptr, bph, nb);
    dec_edge_kernel<<<1024, 256>>>(uph, bph, label_src, label_dst, dec_w2, dec_b2, out, EL);
}

// round 7
// speedup vs baseline: 1.7336x; 1.0707x over previous
#include <cuda_runtime.h>
#include <cuda_fp16.h>
#include <cstdint>
#include <cstddef>

#define NU_MAX 100000
#define NB_MAX 50000
#define E_MAX  2000000
#define C 64
#define H 128

// ---------------- device scratch (static, allocation-free) -----------
__device__ float g_u0[NU_MAX * C];
__device__ float g_b0[NB_MAX * C];
__device__ float g_u1[NU_MAX * C];
__device__ float g_b1[NB_MAX * C];
__device__ float g_u2[NU_MAX * C];
__device__ float g_b2[NB_MAX * C];
__device__ __half g_u0h[NU_MAX * C];
__device__ __half g_b0h[NB_MAX * C];
__device__ __half g_u1h[NU_MAX * C];
__device__ __half g_b1h[NB_MAX * C];
__device__ __half g_uph[NU_MAX * H];
__device__ __half g_bph[NB_MAX * H];
// CSR structures
__device__ int g_deg_u[NU_MAX];
__device__ int g_deg_b[NB_MAX];
__device__ int g_off_u[NU_MAX];
__device__ int g_off_b[NB_MAX];
__device__ int g_cur_u[NU_MAX];
__device__ int g_cur_b[NB_MAX];
__device__ int g_nbr_b_of_u[E_MAX];
__device__ int g_nbr_u_of_b[E_MAX];
__device__ int g_counters[2];

static __device__ __forceinline__ uint2 pack_half4(float a, float b, float c, float d) {
    __half2 h01 = __floats2half2_rn(a, b);
    __half2 h23 = __floats2half2_rn(c, d);
    uint2 r;
    r.x = *reinterpret_cast<unsigned*>(&h01);
    r.y = *reinterpret_cast<unsigned*>(&h23);
    return r;
}

// ---------------- utility ----------------
__global__ void zero_all_kernel(int* __restrict__ a, int na,
                                int* __restrict__ b, int nb_,
                                int* __restrict__ c, int nc) {
    int i = blockIdx.x * blockDim.x + threadIdx.x;
    if (i < na) a[i] = 0;
    if (i < nb_) b[i] = 0;
    if (i < nc) c[i] = 0;
}

// 8 edges per thread, int4 loads for MLP
__global__ void deg_kernel(const int* __restrict__ src, const int* __restrict__ dst,
                           int* __restrict__ degu, int* __restrict__ degb, int E) {
    int t = blockIdx.x * blockDim.x + threadIdx.x;
    int i0 = t * 8;
    if (i0 + 7 < E) {
        int4 s0 = __ldg(reinterpret_cast<const int4*>(src) + t * 2);
        int4 s1 = __ldg(reinterpret_cast<const int4*>(src) + t * 2 + 1);
        int4 d0 = __ldg(reinterpret_cast<const int4*>(dst) + t * 2);
        int4 d1 = __ldg(reinterpret_cast<const int4*>(dst) + t * 2 + 1);
        atomicAdd(degu + s0.x, 1); atomicAdd(degu + s0.y, 1);
        atomicAdd(degu + s0.z, 1); atomicAdd(degu + s0.w, 1);
        atomicAdd(degu + s1.x, 1); atomicAdd(degu + s1.y, 1);
        atomicAdd(degu + s1.z, 1); atomicAdd(degu + s1.w, 1);
        atomicAdd(degb + d0.x, 1); atomicAdd(degb + d0.y, 1);
        atomicAdd(degb + d0.z, 1); atomicAdd(degb + d0.w, 1);
        atomicAdd(degb + d1.x, 1); atomicAdd(degb + d1.y, 1);
        atomicAdd(degb + d1.z, 1); atomicAdd(degb + d1.w, 1);
    } else {
        for (int k = 0; k < 8; k++) {
            int i = i0 + k;
            if (i < E) {
                atomicAdd(degu + __ldg(src + i), 1);
                atomicAdd(degb + __ldg(dst + i), 1);
            }
        }
    }
}

// fused parallel segment allocation for both sides.
__global__ void alloc_offsets2_kernel(const int* __restrict__ degu, int* __restrict__ offu,
                                      int* __restrict__ curu,
                                      const int* __restrict__ degb, int* __restrict__ offb,
                                      int* __restrict__ curb,
                                      int* __restrict__ counters, int nu, int nb, int gu) {
    bool isU = (int)blockIdx.x < gu;
    const int* deg = isU ? degu : degb;
    int* off = isU ? offu : offb;
    int* cur = isU ? curu : curb;
    int* counter = counters + (isU ? 0 : 1);
    int n = isU ? nu : nb;
    int bid = isU ? blockIdx.x : blockIdx.x - gu;

    __shared__ int s_warp[32];
    __shared__ int s_base;
    int tid = threadIdx.x, lane = tid & 31, wid = tid >> 5;
    int i = bid * 1024 + tid;
    int v = (i < n) ? deg[i] : 0;
    int x = v;
    #pragma unroll
    for (int o = 1; o < 32; o <<= 1) {
        int t = __shfl_up_sync(0xFFFFFFFFu, x, o);
        if (lane >= o) x += t;
    }
    if (lane == 31) s_warp[wid] = x;
    __syncthreads();
    if (wid == 0) {
        int w = s_warp[lane];
        #pragma unroll
        for (int o = 1; o < 32; o <<= 1) {
            int t = __shfl_up_sync(0xFFFFFFFFu, w, o);
            if (lane >= o) w += t;
        }
        s_warp[lane] = w;
    }
    __syncthreads();
    if (tid == 0) s_base = atomicAdd(counter, s_warp[31]);
    __syncthreads();
    int warpoff = (wid == 0) ? 0 : s_warp[wid - 1];
    int exc = s_base + warpoff + x - v;
    if (i < n) { off[i] = exc; cur[i] = exc; }
}

// 4 edges per thread, int4 loads, 8 independent atomic chains
__global__ void scatter_kernel(const int* __restrict__ src, const int* __restrict__ dst,
                               int* __restrict__ curu, int* __restrict__ curb,
                               int* __restrict__ nbr_b_of_u, int* __restrict__ nbr_u_of_b,
                               int E) {
    int t = blockIdx.x * blockDim.x + threadIdx.x;
    int i0 = t * 4;
    if (i0 + 3 < E) {
        int4 s4 = __ldg(reinterpret_cast<const int4*>(src) + t);
        int4 d4 = __ldg(reinterpret_cast<const int4*>(dst) + t);
        int pu0 = atomicAdd(curu + s4.x, 1);
        int pu1 = atomicAdd(curu + s4.y, 1);
        int pu2 = atomicAdd(curu + s4.z, 1);
        int pu3 = atomicAdd(curu + s4.w, 1);
        int pb0 = atomicAdd(curb + d4.x, 1);
        int pb1 = atomicAdd(curb + d4.y, 1);
        int pb2 = atomicAdd(curb + d4.z, 1);
        int pb3 = atomicAdd(curb + d4.w, 1);
        nbr_b_of_u[pu0] = d4.x;
        nbr_b_of_u[pu1] = d4.y;
        nbr_b_of_u[pu2] = d4.z;
        nbr_b_of_u[pu3] = d4.w;
        nbr_u_of_b[pb0] = s4.x;
        nbr_u_of_b[pb1] = s4.y;
        nbr_u_of_b[pb2] = s4.z;
        nbr_u_of_b[pb3] = s4.w;
    } else {
        for (int k = 0; k < 4; k++) {
            int i = i0 + k;
            if (i < E) {
                int s = __ldg(src + i), d = __ldg(dst + i);
                int pu = atomicAdd(curu + s, 1);
                nbr_b_of_u[pu] = d;
                int pb = atomicAdd(curb + d, 1);
                nbr_u_of_b[pb] = s;
            }
        }
    }
}

// ---------------- input projections (emit fp32 + fp16) ----------------
__global__ void user_proj_kernel(const float* __restrict__ x, const float* __restrict__ w,
                                 const float* __restrict__ b, float* __restrict__ out,
                                 __half* __restrict__ outh, int n) {
    unsigned i = blockIdx.x * blockDim.x + threadIdx.x;
    if (i >= (unsigned)n * 16u) return;
    unsigned node = i >> 4, j4 = (i & 15u) * 4;
    const float* xr = x + (size_t)node * 3;
    float x0 = __ldg(xr), x1 = __ldg(xr + 1), x2 = __ldg(xr + 2);
    float4 bb = __ldg(reinterpret_cast<const float4*>(b + j4));
    float4 w0 = __ldg(reinterpret_cast<const float4*>(w + j4));
    float4 w1 = __ldg(reinterpret_cast<const float4*>(w + 64 + j4));
    float4 w2 = __ldg(reinterpret_cast<const float4*>(w + 128 + j4));
    float4 r;
    r.x = bb.x + x0 * w0.x + x1 * w1.x + x2 * w2.x;
    r.y = bb.y + x0 * w0.y + x1 * w1.y + x2 * w2.y;
    r.z = bb.z + x0 * w0.z + x1 * w1.z + x2 * w2.z;
    r.w = bb.w + x0 * w0.w + x1 * w1.w + x2 * w2.w;
    *reinterpret_cast<float4*>(out + (size_t)node * 64 + j4) = r;
    *reinterpret_cast<uint2*>(outh + (size_t)node * 64 + j4) = pack_half4(r.x, r.y, r.z, r.w);
}

// book: [n,384] @ [384,64] + b, full weights in dynamic smem, grid-stride.
__global__ void book_proj_kernel(const float* __restrict__ x, const float* __restrict__ w,
                                 const float* __restrict__ bias, float* __restrict__ out,
                                 __half* __restrict__ outh, int n) {
    extern __shared__ float dsm[];
    float* s_w = dsm;                 // 384*64
    float* s_rc = dsm + 384 * 64;     // 32 rows x 96
    int tid = threadIdx.x, lane = tid & 31, wid = tid >> 5;
    const float4* wsrc = reinterpret_cast<const float4*>(w);
    float4* wdst = reinterpret_cast<float4*>(s_w);
    for (int i = tid; i < 384 * 64 / 4; i += 256) wdst[i] = __ldg(wsrc + i);
    float2 bb = make_float2(__ldg(bias + lane * 2), __ldg(bias + lane * 2 + 1));
    __syncthreads();

    for (int g = blockIdx.x * 32; g < n; g += gridDim.x * 32) {
        int node0 = g + wid * 4;
        float2 acc[4];
        #pragma unroll
        for (int r = 0; r < 4; r++) acc[r] = bb;
        for (int ch = 0; ch < 4; ch++) {
            #pragma unroll
            for (int r = 0; r < 4; r++) {
                int nd = node0 + r;
                if (nd < n) {
                    const float* xr = x + (size_t)nd * 384 + ch * 96;
                    float* dst = s_rc + (wid * 4 + r) * 96;
                    dst[lane] = __ldg(xr + lane);
                    dst[lane + 32] = __ldg(xr + lane + 32);
                    dst[lane + 64] = __ldg(xr + lane + 64);
                }
            }
            __syncwarp();
            const float* wch = s_w + ch * 96 * 64;
            #pragma unroll 8
            for (int k = 0; k < 96; k++) {
                float2 wv = *reinterpret_cast<const float2*>(wch + k * 64 + lane * 2);
                #pragma unroll
                for (int r = 0; r < 4; r++) {
                    float xv = s_rc[(wid * 4 + r) * 96 + k];
                    acc[r].x += xv * wv.x;
                    acc[r].y += xv * wv.y;
                }
            }
            __syncwarp();
        }
        #pragma unroll
        for (int r = 0; r < 4; r++) {
            int nd = node0 + r;
            if (nd < n) {
                *reinterpret_cast<float2*>(out + (size_t)nd * 64 + lane * 2) = acc[r];
                __half2 h = __floats2half2_rn(acc[r].x, acc[r].y);
                *reinterpret_cast<unsigned*>(outh + (size_t)nd * 64 + lane * 2) =
                    *reinterpret_cast<unsigned*>(&h);
            }
        }
    }
}

// ---------------- fused SAGE: half-warp per node, pipelined fp16 gather --------------
template <bool RELU, bool EMIT_H>
__global__ void __launch_bounds__(256)
sage_fused_kernel(const __half* __restrict__ xsrc, const float* __restrict__ xdst,
                  const int* __restrict__ offs, const int* __restrict__ degs,
                  const int* __restrict__ nbr,
                  const float* __restrict__ wl, const float* __restrict__ bias,
                  const float* __restrict__ wr,
                  float* __restrict__ out, __half* __restrict__ outh, int n) {
    __shared__ __align__(16) float s_wl[64 * 64];
    __shared__ __align__(16) float s_wr[64 * 64];
    __shared__ float s_b[64];
    __shared__ __align__(16) float s_rows[8][2][132];
    for (int i = threadIdx.x; i < 64 * 64; i += blockDim.x) { s_wl[i] = wl[i]; s_wr[i] = wr[i]; }
    if (threadIdx.x < 64) s_b[threadIdx.x] = bias[threadIdx.x];
    __syncthreads();
    const unsigned FULL = 0xFFFFFFFFu;
    int lane = threadIdx.x & 31, wid = threadIdx.x >> 5;
    int lane16 = lane & 15, half = lane >> 4;

    for (int base = blockIdx.x * 16 + wid * 2; base < n; base += gridDim.x * 16) {
        int node = base + half;
        bool valid = node < n;
        int beg = 0, dg = 0;
        if (valid) { beg = __ldg(offs + node); dg = __ldg(degs + node); }
        int nb_h = (dg + 15) >> 4;
        int nb_o = __shfl_xor_sync(FULL, nb_h, 16);
        int nbatch = max(nb_h, nb_o);

        float4 a0 = make_float4(0.f, 0.f, 0.f, 0.f);
        float4 a1 = make_float4(0.f, 0.f, 0.f, 0.f);
        float4 a2 = make_float4(0.f, 0.f, 0.f, 0.f);
        float4 a3 = make_float4(0.f, 0.f, 0.f, 0.f);

        // prime index pipeline
        int sidx = (lane16 < dg) ? __ldg(nbr + beg + lane16) : 0;
        for (int b = 0; b < nbatch; b++) {
            int rem = dg - b * 16;
            // prefetch next batch's indices
            int sidx_next = 0;
            if (b + 1 < nbatch) {
                int rem2 = dg - (b + 1) * 16;
                sidx_next = (lane16 < rem2) ? __ldg(nbr + beg + (b + 1) * 16 + lane16) : 0;
            }
            // front-batch all 16 row loads (MLP=16)
            uint2 r[16];
            #pragma unroll
            for (int j = 0; j < 16; j++) {
                int s = __shfl_sync(FULL, sidx, j, 16);
                r[j] = __ldg(reinterpret_cast<const uint2*>(xsrc + (size_t)s * 64) + lane16);
            }
            // accumulate (predicated, rotating over 4 accumulators)
            #pragma unroll
            for (int j = 0; j < 16; j += 4) {
                if (j < rem) {
                    float2 lo = __half22float2(*reinterpret_cast<__half2*>(&r[j].x));
                    float2 hi = __half22float2(*reinterpret_cast<__half2*>(&r[j].y));
                    a0.x += lo.x; a0.y += lo.y; a0.z += hi.x; a0.w += hi.y;
                }
                if (j + 1 < rem) {
                    float2 lo = __half22float2(*reinterpret_cast<__half2*>(&r[j + 1].x));
                    float2 hi = __half22float2(*reinterpret_cast<__half2*>(&r[j + 1].y));
                    a1.x += lo.x; a1.y += lo.y; a1.z += hi.x; a1.w += hi.y;
                }
                if (j + 2 < rem) {
                    float2 lo = __half22float2(*reinterpret_cast<__half2*>(&r[j + 2].x));
                    float2 hi = __half22float2(*reinterpret_cast<__half2*>(&r[j + 2].y));
                    a2.x += lo.x; a2.y += lo.y; a2.z += hi.x; a2.w += hi.y;
                }
                if (j + 3 < rem) {
                    float2 lo = __half22float2(*reinterpret_cast<__half2*>(&r[j + 3].x));
                    float2 hi = __half22float2(*reinterpret_cast<__half2*>(&r[j + 3].y));
                    a3.x += lo.x; a3.y += lo.y; a3.z += hi.x; a3.w += hi.y;
                }
            }
            sidx = sidx_next;
        }
        float inv = 1.0f / fmaxf((float)dg, 1.0f);
        float4 mean4;
        mean4.x = (a0.x + a1.x + a2.x + a3.x) * inv;
        mean4.y = (a0.y + a1.y + a2.y + a3.y) * inv;
        mean4.z = (a0.z + a1.z + a2.z + a3.z) * inv;
        mean4.w = (a0.w + a1.w + a2.w + a3.w) * inv;
        float4 xv = make_float4(0.f, 0.f, 0.f, 0.f);
        if (valid)
            xv = *reinterpret_cast<const float4*>(xdst + (size_t)node * 64 + lane16 * 4);
        float* rw = &s_rows[wid][half][0];
        reinterpret_cast<float4*>(rw)[lane16] = mean4;
        reinterpret_cast<float4*>(rw + 64)[lane16] = xv;
        __syncwarp();
        float4 acc = *reinterpret_cast<const float4*>(s_b + lane16 * 4);
        #pragma unroll 8
        for (int k = 0; k < 64; k++) {
            float mk = rw[k];
            float xk = rw[64 + k];
            float4 wlv = *reinterpret_cast<const float4*>(s_wl + k * 64 + lane16 * 4);
            float4 wrv = *reinterpret_cast<const float4*>(s_wr + k * 64 + lane16 * 4);
            acc.x += mk * wlv.x + xk * wrv.x;
            acc.y += mk * wlv.y + xk * wrv.y;
            acc.z += mk * wlv.z + xk * wrv.z;
            acc.w += mk * wlv.w + xk * wrv.w;
        }
        if (RELU) {
            acc.x = fmaxf(acc.x, 0.f); acc.y = fmaxf(acc.y, 0.f);
            acc.z = fmaxf(acc.z, 0.f); acc.w = fmaxf(acc.w, 0.f);
        }
        if (valid) {
            *reinterpret_cast<float4*>(out + (size_t)node * 64 + lane16 * 4) = acc;
            if (EMIT_H)
                *reinterpret_cast<uint2*>(outh + (size_t)node * 64 + lane16 * 4) =
                    pack_half4(acc.x, acc.y, acc.z, acc.w);
        }
        __syncwarp();
    }
}

// ---------------- decoder precompute: out[n,128](fp16) = x[n,64] @ w[64,128] (+bias) --
__global__ void dec_pre_kernel(const float* __restrict__ x, const float* __restrict__ w,
                               const float* __restrict__ bias, __half* __restrict__ out, int n) {
    __shared__ __align__(16) float s_w[64 * 128];
    __shared__ float s_rows[8][64];
    for (int i = threadIdx.x; i < 64 * 128; i += blockDim.x) s_w[i] = w[i];
    __syncthreads();
    int lane = threadIdx.x & 31, wid = threadIdx.x >> 5;
    for (int node = blockIdx.x * 8 + wid; node < n; node += gridDim.x * 8) {
        float2 xv = *reinterpret_cast<const float2*>(x + (size_t)node * 64 + lane * 2);
        s_rows[wid][lane * 2] = xv.x;
        s_rows[wid][lane * 2 + 1] = xv.y;
        __syncwarp();
        float4 acc;
        if (bias) acc = *reinterpret_cast<const float4*>(bias + lane * 4);
        else      acc = make_float4(0.f, 0.f, 0.f, 0.f);
        #pragma unroll 8
        for (int k = 0; k < 64; k++) {
            float xk = s_rows[wid][k];
            float4 wv = *reinterpret_cast<const float4*>(s_w + k * 128 + lane * 4);
            acc.x += xk * wv.x; acc.y += xk * wv.y; acc.z += xk * wv.z; acc.w += xk * wv.w;
        }
        *reinterpret_cast<uint2*>(out + (size_t)node * 128 + lane * 4) =
            pack_half4(acc.x, acc.y, acc.z, acc.w);
        __syncwarp();
    }
}

// ---------------- decoder edge kernel: fp16 tables, 4 edges per warp iteration -------
__global__ void dec_edge_kernel(const __half* __restrict__ Up, const __half* __restrict__ Bp,
                                const int* __restrict__ ls, const int* __restrict__ ld,
                                const float* __restrict__ w2, const float* __restrict__ b2,
                                float* __restrict__ out, int m) {
    __shared__ float s_w2[128];
    if (threadIdx.x < 128) s_w2[threadIdx.x] = w2[threadIdx.x];
    __syncthreads();
    int lane = threadIdx.x & 31;
    int wid = threadIdx.x >> 5;
    float bb = __ldg(b2);
    float wq0 = s_w2[lane * 4], wq1 = s_w2[lane * 4 + 1];
    float wq2 = s_w2[lane * 4 + 2], wq3 = s_w2[lane * 4 + 3];
    int gwarp = blockIdx.x * 8 + wid;
    int stride = gridDim.x * 8;
    for (int e0 = gwarp * 4; e0 < m; e0 += stride * 4) {
        float dots[4];
        #pragma unroll
        for (int q = 0; q < 4; q++) {
            int e = e0 + q;
            float dot = 0.f;
            if (e < m) {
                int s = __ldg(ls + e);
                int d = __ldg(ld + e);
                uint2 ra = __ldg(reinterpret_cast<const uint2*>(Up + (size_t)s * 128) + lane);
                uint2 rb = __ldg(reinterpret_cast<const uint2*>(Bp + (size_t)d * 128) + lane);
                float2 a01 = __half22float2(*reinterpret_cast<__half2*>(&ra.x));
                float2 a23 = __half22float2(*reinterpret_cast<__half2*>(&ra.y));
                float2 b01 = __half22float2(*reinterpret_cast<__half2*>(&rb.x));
                float2 b23 = __half22float2(*reinterpret_cast<__half2*>(&rb.y));
                dot = fmaxf(a01.x + b01.x, 0.f) * wq0 + fmaxf(a01.y + b01.y, 0.f) * wq1
                    + fmaxf(a23.x + b23.x, 0.f) * wq2 + fmaxf(a23.y + b23.y, 0.f) * wq3;
            }
            dots[q] = dot;
        }
        #pragma unroll
        for (int off = 16; off > 0; off >>= 1) {
            dots[0] += __shfl_xor_sync(0xFFFFFFFFu, dots[0], off);
            dots[1] += __shfl_xor_sync(0xFFFFFFFFu, dots[1], off);
            dots[2] += __shfl_xor_sync(0xFFFFFFFFu, dots[2], off);
            dots[3] += __shfl_xor_sync(0xFFFFFFFFu, dots[3], off);
        }
        if (lane == 0) {
            #pragma unroll
            for (int q = 0; q < 4; q++)
                if (e0 + q < m) out[e0 + q] = dots[q] + bb;
        }
    }
}

// ---------------- host launcher ----------------
extern "C" void kernel_launch(void* const* d_in, const int* in_sizes, int n_in,
                              void* d_out, int out_size) {
    const float* user_x    = (const float*)d_in[0];
    const float* book_x    = (const float*)d_in[1];
    const int*   edge_src  = (const int*)d_in[2];
    const int*   edge_dst  = (const int*)d_in[3];
    const int*   label_src = (const int*)d_in[4];
    const int*   label_dst = (const int*)d_in[5];
    const float* user_lin_w = (const float*)d_in[6];
    const float* user_lin_b = (const float*)d_in[7];
    const float* book_lin_w = (const float*)d_in[8];
    const float* book_lin_b = (const float*)d_in[9];
    const float* w1_ub_l = (const float*)d_in[10];
    const float* b1_ub   = (const float*)d_in[11];
    const float* w1_ub_r = (const float*)d_in[12];
    const float* w1_bu_l = (const float*)d_in[13];
    const float* b1_bu   = (const float*)d_in[14];
    const float* w1_bu_r = (const float*)d_in[15];
    const float* w2_ub_l = (const float*)d_in[16];
    const float* b2_ub   = (const float*)d_in[17];
    const float* w2_ub_r = (const float*)d_in[18];
    const float* w2_bu_l = (const float*)d_in[19];
    const float* b2_bu   = (const float*)d_in[20];
    const float* w2_bu_r = (const float*)d_in[21];
    const float* dec_w1  = (const float*)d_in[22];
    const float* dec_b1  = (const float*)d_in[23];
    const float* dec_w2  = (const float*)d_in[24];
    const float* dec_b2  = (const float*)d_in[25];

    int nu = in_sizes[0] / 3;
    int nb = in_sizes[1] / 384;
    int E  = in_sizes[2];
    int EL = in_sizes[4];
    float* out = (float*)d_out;

    float *u0, *b0, *u1, *b1, *u2, *b2;
    __half *u0h, *b0h, *u1h, *b1h, *uph, *bph;
    int *degu, *degb, *offu, *offb, *curu, *curb, *nbu, *nub, *cnts;
    cudaGetSymbolAddress((void**)&u0, g_u0);
    cudaGetSymbolAddress((void**)&b0, g_b0);
    cudaGetSymbolAddress((void**)&u1, g_u1);
    cudaGetSymbolAddress((void**)&b1, g_b1);
    cudaGetSymbolAddress((void**)&u2, g_u2);
    cudaGetSymbolAddress((void**)&b2, g_b2);
    cudaGetSymbolAddress((void**)&u0h, g_u0h);
    cudaGetSymbolAddress((void**)&b0h, g_b0h);
    cudaGetSymbolAddress((void**)&u1h, g_u1h);
    cudaGetSymbolAddress((void**)&b1h, g_b1h);
    cudaGetSymbolAddress((void**)&uph, g_uph);
    cudaGetSymbolAddress((void**)&bph, g_bph);
    cudaGetSymbolAddress((void**)&degu, g_deg_u);
    cudaGetSymbolAddress((void**)&degb, g_deg_b);
    cudaGetSymbolAddress((void**)&offu, g_off_u);
    cudaGetSymbolAddress((void**)&offb, g_off_b);
    cudaGetSymbolAddress((void**)&curu, g_cur_u);
    cudaGetSymbolAddress((void**)&curb, g_cur_b);
    cudaGetSymbolAddress((void**)&nbu, g_nbr_b_of_u);
    cudaGetSymbolAddress((void**)&nub, g_nbr_u_of_b);
    cudaGetSymbolAddress((void**)&cnts, g_counters);

    static const int BOOK_SMEM = (384 * 64 + 32 * 96) * 4;
    cudaFuncSetAttribute(book_proj_kernel, cudaFuncAttributeMaxDynamicSharedMemorySize, BOOK_SMEM);

    // ---- CSR build ----
    zero_all_kernel<<<(nu + 255) / 256, 256>>>(degu, nu, degb, nb, cnts, 2);
    deg_kernel<<<(E / 8 + 255) / 256, 256>>>(edge_src, edge_dst, degu, degb, E);
    int gu = (nu + 1023) / 1024, gb = (nb + 1023) / 1024;
    alloc_offsets2_kernel<<<gu + gb, 1024>>>(degu, offu, curu, degb, offb, curb, cnts, nu, nb, gu);
    scatter_kernel<<<(E / 4 + 255) / 256, 256>>>(edge_src, edge_dst, curu, curb, nbu, nub, E);

    // ---- input projections ----
    {
        unsigned t = (unsigned)nu * 16u;
        user_proj_kernel<<<(t + 255) / 256, 256>>>(user_x, user_lin_w, user_lin_b, u0, u0h, nu);
    }
    book_proj_kernel<<<296, 256, BOOK_SMEM>>>(book_x, book_lin_w, book_lin_b, b0, b0h, nb);

    // ---- layer 1 (fused gather+transform, relu, emit fp16) ----
    sage_fused_kernel<true, true><<<888, 256>>>(u0h, b0, offb, degb, nub, w1_ub_l, b1_ub, w1_ub_r, b1, b1h, nb);
    sage_fused_kernel<true, true><<<888, 256>>>(b0h, u0, offu, degu, nbu, w1_bu_l, b1_bu, w1_bu_r, u1, u1h, nu);

    // ---- layer 2 (no relu, fp32 only) ----
    sage_fused_kernel<false, false><<<888, 256>>>(u1h, b1, offb, degb, nub, w2_ub_l, b2_ub, w2_ub_r, b2, nullptr, nb);
    sage_fused_kernel<false, false><<<888, 256>>>(b1h, u1, offu, degu, nbu, w2_bu_l, b2_bu, w2_bu_r, u2, nullptr, nu);

    // ---- decoder ----
    dec_pre_kernel<<<888, 256>>>(u2, dec_w1, dec_b1, uph, nu);
    dec_pre_kernel<<<888, 256>>>(b2, dec_w1 + 64 * 128, nullptr, bph, nb);
    dec_edge_kernel<<<1024, 256>>>(uph, bph, label_src, label_dst, dec_w2, dec_b2, out, EL);
}

// round 9
// speedup vs baseline: 1.9943x; 1.1504x over previous
#include <cuda_runtime.h>
#include <cuda_fp16.h>
#include <cstdint>
#include <cstddef>

#define NU_MAX 100000
#define NB_MAX 50000
#define E_MAX  2000000
#define C 64
#define H 128

// ---------------- device scratch (static, allocation-free) -----------
__device__ float g_u0[NU_MAX * C];
__device__ float g_b0[NB_MAX * C];
__device__ float g_u1[NU_MAX * C];
__device__ float g_b1[NB_MAX * C];
__device__ float g_u2[NU_MAX * C];
__device__ float g_b2[NB_MAX * C];
__device__ float g_mu[NU_MAX * C];     // fp32 mean buffers
__device__ float g_mb[NB_MAX * C];
__device__ __half g_u0h[NU_MAX * C];
__device__ __half g_b0h[NB_MAX * C];
__device__ __half g_u1h[NU_MAX * C];
__device__ __half g_b1h[NB_MAX * C];
__device__ __half g_uph[NU_MAX * H];
__device__ __half g_bph[NB_MAX * H];
// CSR structures
__device__ int g_deg_u[NU_MAX];
__device__ int g_deg_b[NB_MAX];
__device__ int g_off_u[NU_MAX];
__device__ int g_off_b[NB_MAX];
__device__ int g_cur_u[NU_MAX];
__device__ int g_cur_b[NB_MAX];
__device__ int g_nbr_b_of_u[E_MAX];
__device__ int g_nbr_u_of_b[E_MAX];
__device__ int g_counters[2];

static __device__ __forceinline__ uint2 pack_half4(float a, float b, float c, float d) {
    __half2 h01 = __floats2half2_rn(a, b);
    __half2 h23 = __floats2half2_rn(c, d);
    uint2 r;
    r.x = *reinterpret_cast<unsigned*>(&h01);
    r.y = *reinterpret_cast<unsigned*>(&h23);
    return r;
}

// ---------------- utility ----------------
__global__ void zero_all_kernel(int* __restrict__ a, int na,
                                int* __restrict__ b, int nb_,
                                int* __restrict__ c, int nc) {
    int i = blockIdx.x * blockDim.x + threadIdx.x;
    if (i < na) a[i] = 0;
    if (i < nb_) b[i] = 0;
    if (i < nc) c[i] = 0;
}

// 8 edges per thread, int4 loads for MLP
__global__ void deg_kernel(const int* __restrict__ src, const int* __restrict__ dst,
                           int* __restrict__ degu, int* __restrict__ degb, int E) {
    int t = blockIdx.x * blockDim.x + threadIdx.x;
    int i0 = t * 8;
    if (i0 + 7 < E) {
        int4 s0 = __ldg(reinterpret_cast<const int4*>(src) + t * 2);
        int4 s1 = __ldg(reinterpret_cast<const int4*>(src) + t * 2 + 1);
        int4 d0 = __ldg(reinterpret_cast<const int4*>(dst) + t * 2);
        int4 d1 = __ldg(reinterpret_cast<const int4*>(dst) + t * 2 + 1);
        atomicAdd(degu + s0.x, 1); atomicAdd(degu + s0.y, 1);
        atomicAdd(degu + s0.z, 1); atomicAdd(degu + s0.w, 1);
        atomicAdd(degu + s1.x, 1); atomicAdd(degu + s1.y, 1);
        atomicAdd(degu + s1.z, 1); atomicAdd(degu + s1.w, 1);
        atomicAdd(degb + d0.x, 1); atomicAdd(degb + d0.y, 1);
        atomicAdd(degb + d0.z, 1); atomicAdd(degb + d0.w, 1);
        atomicAdd(degb + d1.x, 1); atomicAdd(degb + d1.y, 1);
        atomicAdd(degb + d1.z, 1); atomicAdd(degb + d1.w, 1);
    } else {
        for (int k = 0; k < 8; k++) {
            int i = i0 + k;
            if (i < E) {
                atomicAdd(degu + __ldg(src + i), 1);
                atomicAdd(degb + __ldg(dst + i), 1);
            }
        }
    }
}

// fused parallel segment allocation for both sides.
__global__ void alloc_offsets2_kernel(const int* __restrict__ degu, int* __restrict__ offu,
                                      int* __restrict__ curu,
                                      const int* __restrict__ degb, int* __restrict__ offb,
                                      int* __restrict__ curb,
                                      int* __restrict__ counters, int nu, int nb, int gu) {
    bool isU = (int)blockIdx.x < gu;
    const int* deg = isU ? degu : degb;
    int* off = isU ? offu : offb;
    int* cur = isU ? curu : curb;
    int* counter = counters + (isU ? 0 : 1);
    int n = isU ? nu : nb;
    int bid = isU ? blockIdx.x : blockIdx.x - gu;

    __shared__ int s_warp[32];
    __shared__ int s_base;
    int tid = threadIdx.x, lane = tid & 31, wid = tid >> 5;
    int i = bid * 1024 + tid;
    int v = (i < n) ? deg[i] : 0;
    int x = v;
    #pragma unroll
    for (int o = 1; o < 32; o <<= 1) {
        int t = __shfl_up_sync(0xFFFFFFFFu, x, o);
        if (lane >= o) x += t;
    }
    if (lane == 31) s_warp[wid] = x;
    __syncthreads();
    if (wid == 0) {
        int w = s_warp[lane];
        #pragma unroll
        for (int o = 1; o < 32; o <<= 1) {
            int t = __shfl_up_sync(0xFFFFFFFFu, w, o);
            if (lane >= o) w += t;
        }
        s_warp[lane] = w;
    }
    __syncthreads();
    if (tid == 0) s_base = atomicAdd(counter, s_warp[31]);
    __syncthreads();
    int warpoff = (wid == 0) ? 0 : s_warp[wid - 1];
    int exc = s_base + warpoff + x - v;
    if (i < n) { off[i] = exc; cur[i] = exc; }
}

// 4 edges per thread, int4 loads, 8 independent atomic chains
__global__ void scatter_kernel(const int* __restrict__ src, const int* __restrict__ dst,
                               int* __restrict__ curu, int* __restrict__ curb,
                               int* __restrict__ nbr_b_of_u, int* __restrict__ nbr_u_of_b,
                               int E) {
    int t = blockIdx.x * blockDim.x + threadIdx.x;
    int i0 = t * 4;
    if (i0 + 3 < E) {
        int4 s4 = __ldg(reinterpret_cast<const int4*>(src) + t);
        int4 d4 = __ldg(reinterpret_cast<const int4*>(dst) + t);
        int pu0 = atomicAdd(curu + s4.x, 1);
        int pu1 = atomicAdd(curu + s4.y, 1);
        int pu2 = atomicAdd(curu + s4.z, 1);
        int pu3 = atomicAdd(curu + s4.w, 1);
        int pb0 = atomicAdd(curb + d4.x, 1);
        int pb1 = atomicAdd(curb + d4.y, 1);
        int pb2 = atomicAdd(curb + d4.z, 1);
        int pb3 = atomicAdd(curb + d4.w, 1);
        nbr_b_of_u[pu0] = d4.x;
        nbr_b_of_u[pu1] = d4.y;
        nbr_b_of_u[pu2] = d4.z;
        nbr_b_of_u[pu3] = d4.w;
        nbr_u_of_b[pb0] = s4.x;
        nbr_u_of_b[pb1] = s4.y;
        nbr_u_of_b[pb2] = s4.z;
        nbr_u_of_b[pb3] = s4.w;
    } else {
        for (int k = 0; k < 4; k++) {
            int i = i0 + k;
            if (i < E) {
                int s = __ldg(src + i), d = __ldg(dst + i);
                int pu = atomicAdd(curu + s, 1);
                nbr_b_of_u[pu] = d;
                int pb = atomicAdd(curb + d, 1);
                nbr_u_of_b[pb] = s;
            }
        }
    }
}

// ---------------- input projections (emit fp32 + fp16) ----------------
__global__ void user_proj_kernel(const float* __restrict__ x, const float* __restrict__ w,
                                 const float* __restrict__ b, float* __restrict__ out,
                                 __half* __restrict__ outh, int n) {
    unsigned i = blockIdx.x * blockDim.x + threadIdx.x;
    if (i >= (unsigned)n * 16u) return;
    unsigned node = i >> 4, j4 = (i & 15u) * 4;
    const float* xr = x + (size_t)node * 3;
    float x0 = __ldg(xr), x1 = __ldg(xr + 1), x2 = __ldg(xr + 2);
    float4 bb = __ldg(reinterpret_cast<const float4*>(b + j4));
    float4 w0 = __ldg(reinterpret_cast<const float4*>(w + j4));
    float4 w1 = __ldg(reinterpret_cast<const float4*>(w + 64 + j4));
    float4 w2 = __ldg(reinterpret_cast<const float4*>(w + 128 + j4));
    float4 r;
    r.x = bb.x + x0 * w0.x + x1 * w1.x + x2 * w2.x;
    r.y = bb.y + x0 * w0.y + x1 * w1.y + x2 * w2.y;
    r.z = bb.z + x0 * w0.z + x1 * w1.z + x2 * w2.z;
    r.w = bb.w + x0 * w0.w + x1 * w1.w + x2 * w2.w;
    *reinterpret_cast<float4*>(out + (size_t)node * 64 + j4) = r;
    *reinterpret_cast<uint2*>(outh + (size_t)node * 64 + j4) = pack_half4(r.x, r.y, r.z, r.w);
}

// book: [n,384] @ [384,64] + b, full weights in dynamic smem, grid-stride.
__global__ void book_proj_kernel(const float* __restrict__ x, const float* __restrict__ w,
                                 const float* __restrict__ bias, float* __restrict__ out,
                                 __half* __restrict__ outh, int n) {
    extern __shared__ float dsm[];
    float* s_w = dsm;                 // 384*64
    float* s_rc = dsm + 384 * 64;     // 32 rows x 96
    int tid = threadIdx.x, lane = tid & 31, wid = tid >> 5;
    const float4* wsrc = reinterpret_cast<const float4*>(w);
    float4* wdst = reinterpret_cast<float4*>(s_w);
    for (int i = tid; i < 384 * 64 / 4; i += 256) wdst[i] = __ldg(wsrc + i);
    float2 bb = make_float2(__ldg(bias + lane * 2), __ldg(bias + lane * 2 + 1));
    __syncthreads();

    for (int g = blockIdx.x * 32; g < n; g += gridDim.x * 32) {
        int node0 = g + wid * 4;
        float2 acc[4];
        #pragma unroll
        for (int r = 0; r < 4; r++) acc[r] = bb;
        for (int ch = 0; ch < 4; ch++) {
            #pragma unroll
            for (int r = 0; r < 4; r++) {
                int nd = node0 + r;
                if (nd < n) {
                    const float* xr = x + (size_t)nd * 384 + ch * 96;
                    float* dst = s_rc + (wid * 4 + r) * 96;
                    dst[lane] = __ldg(xr + lane);
                    dst[lane + 32] = __ldg(xr + lane + 32);
                    dst[lane + 64] = __ldg(xr + lane + 64);
                }
            }
            __syncwarp();
            const float* wch = s_w + ch * 96 * 64;
            #pragma unroll 8
            for (int k = 0; k < 96; k++) {
                float2 wv = *reinterpret_cast<const float2*>(wch + k * 64 + lane * 2);
                #pragma unroll
                for (int r = 0; r < 4; r++) {
                    float xv = s_rc[(wid * 4 + r) * 96 + k];
                    acc[r].x += xv * wv.x;
                    acc[r].y += xv * wv.y;
                }
            }
            __syncwarp();
        }
        #pragma unroll
        for (int r = 0; r < 4; r++) {
            int nd = node0 + r;
            if (nd < n) {
                *reinterpret_cast<float2*>(out + (size_t)nd * 64 + lane * 2) = acc[r];
                __half2 h = __floats2half2_rn(acc[r].x, acc[r].y);
                *reinterpret_cast<unsigned*>(outh + (size_t)nd * 64 + lane * 2) =
                    *reinterpret_cast<unsigned*>(&h);
            }
        }
    }
}

// ---------------- sage gather: half-warp per node, pipelined fp16, mean -> global ----
__global__ void __launch_bounds__(256)
sage_gather_kernel(const __half* __restrict__ xsrc,
                   const int* __restrict__ offs, const int* __restrict__ degs,
                   const int* __restrict__ nbr, float* __restrict__ mout, int n) {
    const unsigned FULL = 0xFFFFFFFFu;
    int lane = threadIdx.x & 31, wid = threadIdx.x >> 5;
    int lane16 = lane & 15, half = lane >> 4;

    for (int base = blockIdx.x * 16 + wid * 2; base < n; base += gridDim.x * 16) {
        int node = base + half;
        bool valid = node < n;
        int beg = 0, dg = 0;
        if (valid) { beg = __ldg(offs + node); dg = __ldg(degs + node); }
        int nb_h = (dg + 15) >> 4;
        int nb_o = __shfl_xor_sync(FULL, nb_h, 16);
        int nbatch = max(nb_h, nb_o);

        float4 a0 = make_float4(0.f, 0.f, 0.f, 0.f);
        float4 a1 = make_float4(0.f, 0.f, 0.f, 0.f);
        float4 a2 = make_float4(0.f, 0.f, 0.f, 0.f);
        float4 a3 = make_float4(0.f, 0.f, 0.f, 0.f);

        int sidx = (lane16 < dg) ? __ldg(nbr + beg + lane16) : 0;
        for (int b = 0; b < nbatch; b++) {
            int rem = dg - b * 16;
            int sidx_next = 0;
            if (b + 1 < nbatch) {
                int rem2 = dg - (b + 1) * 16;
                sidx_next = (lane16 < rem2) ? __ldg(nbr + beg + (b + 1) * 16 + lane16) : 0;
            }
            uint2 r[16];
            #pragma unroll
            for (int j = 0; j < 16; j++) {
                int s = __shfl_sync(FULL, sidx, j, 16);
                r[j] = __ldg(reinterpret_cast<const uint2*>(xsrc + (size_t)s * 64) + lane16);
            }
            #pragma unroll
            for (int j = 0; j < 16; j += 4) {
                if (j < rem) {
                    float2 lo = __half22float2(*reinterpret_cast<__half2*>(&r[j].x));
                    float2 hi = __half22float2(*reinterpret_cast<__half2*>(&r[j].y));
                    a0.x += lo.x; a0.y += lo.y; a0.z += hi.x; a0.w += hi.y;
                }
                if (j + 1 < rem) {
                    float2 lo = __half22float2(*reinterpret_cast<__half2*>(&r[j + 1].x));
                    float2 hi = __half22float2(*reinterpret_cast<__half2*>(&r[j + 1].y));
                    a1.x += lo.x; a1.y += lo.y; a1.z += hi.x; a1.w += hi.y;
                }
                if (j + 2 < rem) {
                    float2 lo = __half22float2(*reinterpret_cast<__half2*>(&r[j + 2].x));
                    float2 hi = __half22float2(*reinterpret_cast<__half2*>(&r[j + 2].y));
                    a2.x += lo.x; a2.y += lo.y; a2.z += hi.x; a2.w += hi.y;
                }
                if (j + 3 < rem) {
                    float2 lo = __half22float2(*reinterpret_cast<__half2*>(&r[j + 3].x));
                    float2 hi = __half22float2(*reinterpret_cast<__half2*>(&r[j + 3].y));
                    a3.x += lo.x; a3.y += lo.y; a3.z += hi.x; a3.w += hi.y;
                }
            }
            sidx = sidx_next;
        }
        if (valid) {
            float inv = 1.0f / fmaxf((float)dg, 1.0f);
            float4 m;
            m.x = (a0.x + a1.x + a2.x + a3.x) * inv;
            m.y = (a0.y + a1.y + a2.y + a3.y) * inv;
            m.z = (a0.z + a1.z + a2.z + a3.z) * inv;
            m.w = (a0.w + a1.w + a2.w + a3.w) * inv;
            *reinterpret_cast<float4*>(mout + (size_t)node * 64 + lane16 * 4) = m;
        }
    }
}

// ---------------- sage transform: staged 64-node GEMM (dynamic smem) -----------------
// out[n][64] = [mean | x] @ [wl ; wr] + bias, optional relu + fp16 emit.
// dynamic smem layout: s_w[128*64] | s_a[64*132] | s_bias[64]
#define SAGE_T_SMEM ((128 * 64 + 64 * 132 + 64) * 4)
template <bool RELU, bool EMIT_H>
__global__ void __launch_bounds__(256)
sage_transform_kernel(const float* __restrict__ M, const float* __restrict__ X,
                      const float* __restrict__ wl, const float* __restrict__ bias,
                      const float* __restrict__ wr,
                      float* __restrict__ out, __half* __restrict__ outh, int n) {
    extern __shared__ __align__(16) float dyn[];
    float* s_w = dyn;                      // 128*64
    float* s_a = dyn + 128 * 64;           // 64*132
    float* s_bias = s_a + 64 * 132;        // 64
    int tid = threadIdx.x;
    for (int i = tid; i < 64 * 64; i += 256) { s_w[i] = wl[i]; s_w[4096 + i] = wr[i]; }
    if (tid < 64) s_bias[tid] = bias[tid];
    int ty = tid >> 4, tx = tid & 15;   // 16x16 grid: 4 nodes x 4 outs each
    int row = tid >> 2, seg = tid & 3;  // staging: 64 rows x 4 segments of 32 floats

    for (int tile = blockIdx.x * 64; tile < n; tile += gridDim.x * 64) {
        __syncthreads();
        {
            int node = tile + row;
            float* dstp = s_a + row * 132 + seg * 32;
            if (node < n) {
                const float* srcp = (seg < 2) ? (M + (size_t)node * 64 + seg * 32)
                                              : (X + (size_t)node * 64 + (seg - 2) * 32);
                #pragma unroll
                for (int q = 0; q < 8; q++)
                    reinterpret_cast<float4*>(dstp)[q] =
                        __ldg(reinterpret_cast<const float4*>(srcp) + q);
            } else {
                #pragma unroll
                for (int q = 0; q < 8; q++)
                    reinterpret_cast<float4*>(dstp)[q] = make_float4(0.f, 0.f, 0.f, 0.f);
            }
        }
        __syncthreads();
        float4 c0 = *reinterpret_cast<const float4*>(s_bias + tx * 4);
        float4 c1 = c0, c2 = c0, c3 = c0;
        const float* a0p = s_a + (ty * 4 + 0) * 132;
        const float* a1p = s_a + (ty * 4 + 1) * 132;
        const float* a2p = s_a + (ty * 4 + 2) * 132;
        const float* a3p = s_a + (ty * 4 + 3) * 132;
        #pragma unroll 4
        for (int k = 0; k < 128; k++) {
            float4 w = *reinterpret_cast<const float4*>(s_w + k * 64 + tx * 4);
            float a0 = a0p[k], a1 = a1p[k], a2 = a2p[k], a3 = a3p[k];
            c0.x += a0 * w.x; c0.y += a0 * w.y; c0.z += a0 * w.z; c0.w += a0 * w.w;
            c1.x += a1 * w.x; c1.y += a1 * w.y; c1.z += a1 * w.z; c1.w += a1 * w.w;
            c2.x += a2 * w.x; c2.y += a2 * w.y; c2.z += a2 * w.z; c2.w += a2 * w.w;
            c3.x += a3 * w.x; c3.y += a3 * w.y; c3.z += a3 * w.z; c3.w += a3 * w.w;
        }
        if (RELU) {
            c0.x = fmaxf(c0.x, 0.f); c0.y = fmaxf(c0.y, 0.f); c0.z = fmaxf(c0.z, 0.f); c0.w = fmaxf(c0.w, 0.f);
            c1.x = fmaxf(c1.x, 0.f); c1.y = fmaxf(c1.y, 0.f); c1.z = fmaxf(c1.z, 0.f); c1.w = fmaxf(c1.w, 0.f);
            c2.x = fmaxf(c2.x, 0.f); c2.y = fmaxf(c2.y, 0.f); c2.z = fmaxf(c2.z, 0.f); c2.w = fmaxf(c2.w, 0.f);
            c3.x = fmaxf(c3.x, 0.f); c3.y = fmaxf(c3.y, 0.f); c3.z = fmaxf(c3.z, 0.f); c3.w = fmaxf(c3.w, 0.f);
        }
        float4 cc[4] = {c0, c1, c2, c3};
        #pragma unroll
        for (int i = 0; i < 4; i++) {
            int nd = tile + ty * 4 + i;
            if (nd < n) {
                *reinterpret_cast<float4*>(out + (size_t)nd * 64 + tx * 4) = cc[i];
                if (EMIT_H)
                    *reinterpret_cast<uint2*>(outh + (size_t)nd * 64 + tx * 4) =
                        pack_half4(cc[i].x, cc[i].y, cc[i].z, cc[i].w);
            }
        }
    }
}

// ---------------- decoder precompute: staged GEMM [64 nodes][64] @ [64][128] ----------
// dynamic smem layout: s_w[64*128] | s_a[64*68] | s_bias[128]
#define DEC_P_SMEM ((64 * 128 + 64 * 68 + 128) * 4)
__global__ void __launch_bounds__(256)
dec_pre_kernel(const float* __restrict__ x, const float* __restrict__ w,
               const float* __restrict__ bias, __half* __restrict__ out, int n) {
    extern __shared__ __align__(16) float dyn[];
    float* s_w = dyn;                      // 64*128
    float* s_a = dyn + 64 * 128;           // 64*68
    float* s_bias = s_a + 64 * 68;         // 128
    int tid = threadIdx.x;
    for (int i = tid; i < 64 * 128; i += 256) s_w[i] = w[i];
    if (tid < 128) s_bias[tid] = bias ? bias[tid] : 0.f;
    int ty = tid >> 5, tx = tid & 31;   // 8 warps: 8 nodes x (32 lanes x 4 outs)
    int row = tid >> 2, seg = tid & 3;  // staging: 64 rows x 4 segs of 16 floats

    for (int tile = blockIdx.x * 64; tile < n; tile += gridDim.x * 64) {
        __syncthreads();
        {
            int node = tile + row;
            float* dstp = s_a + row * 68 + seg * 16;
            if (node < n) {
                const float4* srcp = reinterpret_cast<const float4*>(x + (size_t)node * 64 + seg * 16);
                #pragma unroll
                for (int q = 0; q < 4; q++)
                    reinterpret_cast<float4*>(dstp)[q] = __ldg(srcp + q);
            } else {
                #pragma unroll
                for (int q = 0; q < 4; q++)
                    reinterpret_cast<float4*>(dstp)[q] = make_float4(0.f, 0.f, 0.f, 0.f);
            }
        }
        __syncthreads();
        float4 b4 = *reinterpret_cast<const float4*>(s_bias + tx * 4);
        float4 c[8];
        #pragma unroll
        for (int i = 0; i < 8; i++) c[i] = b4;
        #pragma unroll 2
        for (int k = 0; k < 64; k++) {
            float4 w4 = *reinterpret_cast<const float4*>(s_w + k * 128 + tx * 4);
            #pragma unroll
            for (int i = 0; i < 8; i++) {
                float a = s_a[(ty * 8 + i) * 68 + k];
                c[i].x += a * w4.x; c[i].y += a * w4.y; c[i].z += a * w4.z; c[i].w += a * w4.w;
            }
        }
        #pragma unroll
        for (int i = 0; i < 8; i++) {
            int nd = tile + ty * 8 + i;
            if (nd < n)
                *reinterpret_cast<uint2*>(out + (size_t)nd * 128 + tx * 4) =
                    pack_half4(c[i].x, c[i].y, c[i].z, c[i].w);
        }
    }
}

// ---------------- decoder edge kernel: fp16 tables, 4 edges per warp iteration -------
__global__ void dec_edge_kernel(const __half* __restrict__ Up, const __half* __restrict__ Bp,
                                const int* __restrict__ ls, const int* __restrict__ ld,
                                const float* __restrict__ w2, const float* __restrict__ b2,
                                float* __restrict__ out, int m) {
    __shared__ float s_w2[128];
    if (threadIdx.x < 128) s_w2[threadIdx.x] = w2[threadIdx.x];
    __syncthreads();
    int lane = threadIdx.x & 31;
    int wid = threadIdx.x >> 5;
    float bb = __ldg(b2);
    float wq0 = s_w2[lane * 4], wq1 = s_w2[lane * 4 + 1];
    float wq2 = s_w2[lane * 4 + 2], wq3 = s_w2[lane * 4 + 3];
    int gwarp = blockIdx.x * 8 + wid;
    int stride = gridDim.x * 8;
    for (int e0 = gwarp * 4; e0 < m; e0 += stride * 4) {
        float dots[4];
        #pragma unroll
        for (int q = 0; q < 4; q++) {
            int e = e0 + q;
            float dot = 0.f;
            if (e < m) {
                int s = __ldg(ls + e);
                int d = __ldg(ld + e);
                uint2 ra = __ldg(reinterpret_cast<const uint2*>(Up + (size_t)s * 128) + lane);
                uint2 rb = __ldg(reinterpret_cast<const uint2*>(Bp + (size_t)d * 128) + lane);
                float2 a01 = __half22float2(*reinterpret_cast<__half2*>(&ra.x));
                float2 a23 = __half22float2(*reinterpret_cast<__half2*>(&ra.y));
                float2 b01 = __half22float2(*reinterpret_cast<__half2*>(&rb.x));
                float2 b23 = __half22float2(*reinterpret_cast<__half2*>(&rb.y));
                dot = fmaxf(a01.x + b01.x, 0.f) * wq0 + fmaxf(a01.y + b01.y, 0.f) * wq1
                    + fmaxf(a23.x + b23.x, 0.f) * wq2 + fmaxf(a23.y + b23.y, 0.f) * wq3;
            }
            dots[q] = dot;
        }
        #pragma unroll
        for (int off = 16; off > 0; off >>= 1) {
            dots[0] += __shfl_xor_sync(0xFFFFFFFFu, dots[0], off);
            dots[1] += __shfl_xor_sync(0xFFFFFFFFu, dots[1], off);
            dots[2] += __shfl_xor_sync(0xFFFFFFFFu, dots[2], off);
            dots[3] += __shfl_xor_sync(0xFFFFFFFFu, dots[3], off);
        }
        if (lane == 0) {
            #pragma unroll
            for (int q = 0; q < 4; q++)
                if (e0 + q < m) out[e0 + q] = dots[q] + bb;
        }
    }
}

// ---------------- host launcher ----------------
extern "C" void kernel_launch(void* const* d_in, const int* in_sizes, int n_in,
                              void* d_out, int out_size) {
    const float* user_x    = (const float*)d_in[0];
    const float* book_x    = (const float*)d_in[1];
    const int*   edge_src  = (const int*)d_in[2];
    const int*   edge_dst  = (const int*)d_in[3];
    const int*   label_src = (const int*)d_in[4];
    const int*   label_dst = (const int*)d_in[5];
    const float* user_lin_w = (const float*)d_in[6];
    const float* user_lin_b = (const float*)d_in[7];
    const float* book_lin_w = (const float*)d_in[8];
    const float* book_lin_b = (const float*)d_in[9];
    const float* w1_ub_l = (const float*)d_in[10];
    const float* b1_ub   = (const float*)d_in[11];
    const float* w1_ub_r = (const float*)d_in[12];
    const float* w1_bu_l = (const float*)d_in[13];
    const float* b1_bu   = (const float*)d_in[14];
    const float* w1_bu_r = (const float*)d_in[15];
    const float* w2_ub_l = (const float*)d_in[16];
    const float* b2_ub   = (const float*)d_in[17];
    const float* w2_ub_r = (const float*)d_in[18];
    const float* w2_bu_l = (const float*)d_in[19];
    const float* b2_bu   = (const float*)d_in[20];
    const float* w2_bu_r = (const float*)d_in[21];
    const float* dec_w1  = (const float*)d_in[22];
    const float* dec_b1  = (const float*)d_in[23];
    const float* dec_w2  = (const float*)d_in[24];
    const float* dec_b2  = (const float*)d_in[25];

    int nu = in_sizes[0] / 3;
    int nb = in_sizes[1] / 384;
    int E  = in_sizes[2];
    int EL = in_sizes[4];
    float* out = (float*)d_out;

    float *u0, *b0, *u1, *b1, *u2, *b2, *mu, *mb;
    __half *u0h, *b0h, *u1h, *b1h, *uph, *bph;
    int *degu, *degb, *offu, *offb, *curu, *curb, *nbu, *nub, *cnts;
    cudaGetSymbolAddress((void**)&u0, g_u0);
    cudaGetSymbolAddress((void**)&b0, g_b0);
    cudaGetSymbolAddress((void**)&u1, g_u1);
    cudaGetSymbolAddress((void**)&b1, g_b1);
    cudaGetSymbolAddress((void**)&u2, g_u2);
    cudaGetSymbolAddress((void**)&b2, g_b2);
    cudaGetSymbolAddress((void**)&mu, g_mu);
    cudaGetSymbolAddress((void**)&mb, g_mb);
    cudaGetSymbolAddress((void**)&u0h, g_u0h);
    cudaGetSymbolAddress((void**)&b0h, g_b0h);
    cudaGetSymbolAddress((void**)&u1h, g_u1h);
    cudaGetSymbolAddress((void**)&b1h, g_b1h);
    cudaGetSymbolAddress((void**)&uph, g_uph);
    cudaGetSymbolAddress((void**)&bph, g_bph);
    cudaGetSymbolAddress((void**)&degu, g_deg_u);
    cudaGetSymbolAddress((void**)&degb, g_deg_b);
    cudaGetSymbolAddress((void**)&offu, g_off_u);
    cudaGetSymbolAddress((void**)&offb, g_off_b);
    cudaGetSymbolAddress((void**)&curu, g_cur_u);
    cudaGetSymbolAddress((void**)&curb, g_cur_b);
    cudaGetSymbolAddress((void**)&nbu, g_nbr_b_of_u);
    cudaGetSymbolAddress((void**)&nub, g_nbr_u_of_b);
    cudaGetSymbolAddress((void**)&cnts, g_counters);

    static const int BOOK_SMEM = (384 * 64 + 32 * 96) * 4;
    cudaFuncSetAttribute(book_proj_kernel, cudaFuncAttributeMaxDynamicSharedMemorySize, BOOK_SMEM);
    cudaFuncSetAttribute(sage_transform_kernel<true, true>,
                         cudaFuncAttributeMaxDynamicSharedMemorySize, SAGE_T_SMEM);
    cudaFuncSetAttribute(sage_transform_kernel<false, false>,
                         cudaFuncAttributeMaxDynamicSharedMemorySize, SAGE_T_SMEM);
    cudaFuncSetAttribute(dec_pre_kernel, cudaFuncAttributeMaxDynamicSharedMemorySize, DEC_P_SMEM);

    // ---- CSR build ----
    zero_all_kernel<<<(nu + 255) / 256, 256>>>(degu, nu, degb, nb, cnts, 2);
    deg_kernel<<<(E / 8 + 255) / 256, 256>>>(edge_src, edge_dst, degu, degb, E);
    int gu = (nu + 1023) / 1024, gb = (nb + 1023) / 1024;
    alloc_offsets2_kernel<<<gu + gb, 1024>>>(degu, offu, curu, degb, offb, curb, cnts, nu, nb, gu);
    scatter_kernel<<<(E / 4 + 255) / 256, 256>>>(edge_src, edge_dst, curu, curb, nbu, nub, E);

    // ---- input projections ----
    {
        unsigned t = (unsigned)nu * 16u;
        user_proj_kernel<<<(t + 255) / 256, 256>>>(user_x, user_lin_w, user_lin_b, u0, u0h, nu);
    }
    book_proj_kernel<<<296, 256, BOOK_SMEM>>>(book_x, book_lin_w, book_lin_b, b0, b0h, nb);

    // ---- layer 1: gather means, then staged-GEMM transforms (relu + fp16 emit) ----
    sage_gather_kernel<<<1184, 256>>>(u0h, offb, degb, nub, mb, nb);
    sage_gather_kernel<<<1184, 256>>>(b0h, offu, degu, nbu, mu, nu);
    sage_transform_kernel<true, true><<<592, 256, SAGE_T_SMEM>>>(mb, b0, w1_ub_l, b1_ub, w1_ub_r, b1, b1h, nb);
    sage_transform_kernel<true, true><<<592, 256, SAGE_T_SMEM>>>(mu, u0, w1_bu_l, b1_bu, w1_bu_r, u1, u1h, nu);

    // ---- layer 2 (no relu, fp32 only) ----
    sage_gather_kernel<<<1184, 256>>>(u1h, offb, degb, nub, mb, nb);
    sage_gather_kernel<<<1184, 256>>>(b1h, offu, degu, nbu, mu, nu);
    sage_transform_kernel<false, false><<<592, 256, SAGE_T_SMEM>>>(mb, b1, w2_ub_l, b2_ub, w2_ub_r, b2, nullptr, nb);
    sage_transform_kernel<false, false><<<592, 256, SAGE_T_SMEM>>>(mu, u1, w2_bu_l, b2_bu, w2_bu_r, u2, nullptr, nu);

    // ---- decoder ----
    dec_pre_kernel<<<592, 256, DEC_P_SMEM>>>(u2, dec_w1, dec_b1, uph, nu);
    dec_pre_kernel<<<592, 256, DEC_P_SMEM>>>(b2, dec_w1 + 64 * 128, nullptr, bph, nb);
    dec_edge_kernel<<<1024, 256>>>(uph, bph, label_src, label_dst, dec_w2, dec_b2, out, EL);
}